// round 1
// baseline (speedup 1.0000x reference)
#include <cuda_runtime.h>
#include <cuda_bf16.h>
#include <math.h>

// Problem constants
#define Bb   4
#define Tt   1024
#define DIM  2048
#define Hh   16
#define KVH  4
#define Gg   4
#define HD   128

// Scratch (no cudaMalloc allowed)
__device__ float g_q  [Bb * Tt * DIM];        // (B,T,H,HD)
__device__ float g_kv [Bb * Tt * 2 * KVH * HD]; // (B,T,2,KVH,HD)
__device__ float g_ctx[Bb * Tt * DIM];        // (B,T,C)

// ---------------------------------------------------------------------------
// SGEMM: C[M,N] = A[M,K] @ B[K,N], row-major, all dims multiples of tile.
// 128x128 tile, BK=8, 256 threads, 8x8 per thread.
// ---------------------------------------------------------------------------
__global__ __launch_bounds__(256) void sgemm128(const float* __restrict__ A,
                                                const float* __restrict__ B,
                                                float* __restrict__ C,
                                                int M, int N, int K) {
    __shared__ float As[8][128];
    __shared__ float Bs[8][128];

    const int tid = threadIdx.x;
    const int rowBase = blockIdx.y * 128;
    const int colBase = blockIdx.x * 128;
    const int tx = tid & 15;
    const int ty = tid >> 4;

    const int aRow = tid >> 1;          // 0..127
    const int aCol = (tid & 1) * 4;     // 0 or 4
    const int bRow = tid >> 5;          // 0..7
    const int bCol = (tid & 31) * 4;    // 0..124

    float acc[8][8];
#pragma unroll
    for (int i = 0; i < 8; i++)
#pragma unroll
        for (int j = 0; j < 8; j++) acc[i][j] = 0.0f;

    for (int k0 = 0; k0 < K; k0 += 8) {
        float4 av = *(const float4*)&A[(size_t)(rowBase + aRow) * K + k0 + aCol];
        float4 bv = *(const float4*)&B[(size_t)(k0 + bRow) * N + colBase + bCol];
        __syncthreads();
        As[aCol + 0][aRow] = av.x;
        As[aCol + 1][aRow] = av.y;
        As[aCol + 2][aRow] = av.z;
        As[aCol + 3][aRow] = av.w;
        *(float4*)&Bs[bRow][bCol] = bv;
        __syncthreads();

#pragma unroll
        for (int kk = 0; kk < 8; kk++) {
            float a[8], b[8];
            *(float4*)&a[0] = *(float4*)&As[kk][ty * 8];
            *(float4*)&a[4] = *(float4*)&As[kk][ty * 8 + 4];
            *(float4*)&b[0] = *(float4*)&Bs[kk][tx * 8];
            *(float4*)&b[4] = *(float4*)&Bs[kk][tx * 8 + 4];
#pragma unroll
            for (int i = 0; i < 8; i++)
#pragma unroll
                for (int j = 0; j < 8; j++) acc[i][j] = fmaf(a[i], b[j], acc[i][j]);
        }
    }

#pragma unroll
    for (int i = 0; i < 8; i++) {
        int r = rowBase + ty * 8 + i;
        float4 v0 = make_float4(acc[i][0], acc[i][1], acc[i][2], acc[i][3]);
        float4 v1 = make_float4(acc[i][4], acc[i][5], acc[i][6], acc[i][7]);
        *(float4*)&C[(size_t)r * N + colBase + tx * 8]     = v0;
        *(float4*)&C[(size_t)r * N + colBase + tx * 8 + 4] = v1;
    }
}

// ---------------------------------------------------------------------------
// RoPE applied in-place to q (B,T,H,HD) and k half of kv (B,T,2,KVH,HD)
// ---------------------------------------------------------------------------
__global__ void rope_kernel(float* __restrict__ q, float* __restrict__ kvb,
                            const float* __restrict__ cosb,
                            const float* __restrict__ sinb) {
    const int NQ = Bb * Tt * Hh * (HD / 2);
    const int NK = Bb * Tt * KVH * (HD / 2);
    int idx = blockIdx.x * blockDim.x + threadIdx.x;
    if (idx < NQ) {
        int d = idx & 63;
        int rest = idx >> 6;
        int h = rest & (Hh - 1); rest >>= 4;
        int t = rest & (Tt - 1);
        int b = rest >> 10;
        float c = cosb[t * 64 + d];
        float s = sinb[t * 64 + d];
        size_t base = ((size_t)(b * Tt + t) * Hh + h) * HD;
        float u1 = q[base + d];
        float u2 = q[base + 64 + d];
        q[base + d]      = u1 * c - u2 * s;
        q[base + 64 + d] = u1 * s + u2 * c;
    } else if (idx < NQ + NK) {
        int j = idx - NQ;
        int d = j & 63;
        int rest = j >> 6;
        int kvh = rest & (KVH - 1); rest >>= 2;
        int t = rest & (Tt - 1);
        int b = rest >> 10;
        float c = cosb[t * 64 + d];
        float s = sinb[t * 64 + d];
        size_t base = ((size_t)(b * Tt + t) * 2 + 0) * (KVH * HD) + kvh * HD;
        float u1 = kvb[base + d];
        float u2 = kvb[base + 64 + d];
        kvb[base + d]      = u1 * c - u2 * s;
        kvb[base + 64 + d] = u1 * s + u2 * c;
    }
}

// ---------------------------------------------------------------------------
// Flash-style causal attention with GQA.
// grid: (T/64, H, B), block: 256 threads.
// Each CTA: 64 query rows of one head. Online softmax over 64-wide K tiles.
// Thread (ty,tx) [ty=tid/16, tx=tid%16]:
//   S micro-tile: rows ty*4..+3, cols tx*4..+3
//   O accumulator: rows ty*4..+3, d-cols tx*8..+7
// ---------------------------------------------------------------------------
#define PADQ 129
#define PADP 65
#define FLASH_SMEM ((3 * 64 * PADQ + 64 * PADP) * 4)

__global__ __launch_bounds__(256) void flash_kernel(const float* __restrict__ q,
                                                    const float* __restrict__ kvb,
                                                    float* __restrict__ ctx) {
    extern __shared__ float smem[];
    float* Qs = smem;                 // 64 x PADQ
    float* Ks = Qs + 64 * PADQ;       // 64 x PADQ
    float* Vs = Ks + 64 * PADQ;       // 64 x PADQ
    float* Ps = Vs + 64 * PADQ;       // 64 x PADP

    const int qtile = blockIdx.x;
    const int h     = blockIdx.y;
    const int b     = blockIdx.z;
    const int kvh   = h / Gg;
    const int qbase = qtile * 64;

    const int tid = threadIdx.x;
    const int tx = tid & 15;
    const int ty = tid >> 4;
    const int r0 = ty * 4;
    const int c0 = tx * 4;
    const int d0 = tx * 8;

    const float scale = 0.08838834764831845f; // 1/sqrt(128)

    // Load and scale Q tile
    for (int idx = tid; idx < 64 * HD; idx += 256) {
        int r = idx >> 7, d = idx & 127;
        int t = qbase + r;
        Qs[r * PADQ + d] = q[((size_t)(b * Tt + t) * Hh + h) * HD + d] * scale;
    }

    float m_i[4], l_i[4], acc[4][8];
#pragma unroll
    for (int i = 0; i < 4; i++) {
        m_i[i] = -INFINITY;
        l_i[i] = 0.0f;
#pragma unroll
        for (int dd = 0; dd < 8; dd++) acc[i][dd] = 0.0f;
    }
    __syncthreads();

    const int ntiles = qtile + 1;
    for (int kt = 0; kt < ntiles; ++kt) {
        const int kbase = kt * 64;
        // Load K and V tiles
        for (int idx = tid; idx < 64 * HD; idx += 256) {
            int r = idx >> 7, d = idx & 127;
            int t = kbase + r;
            size_t base = ((size_t)(b * Tt + t) * 2) * (KVH * HD) + kvh * HD + d;
            Ks[r * PADQ + d] = kvb[base];
            Vs[r * PADQ + d] = kvb[base + KVH * HD];
        }
        __syncthreads();

        // S = Q K^T (4x4 per thread)
        float s[4][4];
#pragma unroll
        for (int i = 0; i < 4; i++)
#pragma unroll
            for (int j = 0; j < 4; j++) s[i][j] = 0.0f;
        for (int d = 0; d < HD; ++d) {
            float qa[4], kb[4];
#pragma unroll
            for (int i = 0; i < 4; i++) qa[i] = Qs[(r0 + i) * PADQ + d];
#pragma unroll
            for (int j = 0; j < 4; j++) kb[j] = Ks[(c0 + j) * PADQ + d];
#pragma unroll
            for (int i = 0; i < 4; i++)
#pragma unroll
                for (int j = 0; j < 4; j++) s[i][j] = fmaf(qa[i], kb[j], s[i][j]);
        }

        // Causal mask on the diagonal tile
        if (kt == qtile) {
#pragma unroll
            for (int i = 0; i < 4; i++)
#pragma unroll
                for (int j = 0; j < 4; j++)
                    if (kbase + c0 + j > qbase + r0 + i) s[i][j] = -INFINITY;
        }

        // Online softmax row update (rows r0..r0+3; reduce across 16 tx lanes)
#pragma unroll
        for (int i = 0; i < 4; i++) {
            float mx = fmaxf(fmaxf(s[i][0], s[i][1]), fmaxf(s[i][2], s[i][3]));
#pragma unroll
            for (int o = 1; o < 16; o <<= 1)
                mx = fmaxf(mx, __shfl_xor_sync(0xffffffffu, mx, o));
            float m_new = fmaxf(m_i[i], mx);
            float fac = __expf(m_i[i] - m_new);
            float rs = 0.0f;
#pragma unroll
            for (int j = 0; j < 4; j++) {
                float p = __expf(s[i][j] - m_new);
                s[i][j] = p;
                rs += p;
            }
#pragma unroll
            for (int o = 1; o < 16; o <<= 1)
                rs += __shfl_xor_sync(0xffffffffu, rs, o);
            l_i[i] = l_i[i] * fac + rs;
            m_i[i] = m_new;
#pragma unroll
            for (int dd = 0; dd < 8; dd++) acc[i][dd] *= fac;
#pragma unroll
            for (int j = 0; j < 4; j++) Ps[(r0 + i) * PADP + c0 + j] = s[i][j];
        }
        __syncthreads();

        // O += P @ V
        for (int j = 0; j < 64; ++j) {
            float v[8];
#pragma unroll
            for (int dd = 0; dd < 8; dd++) v[dd] = Vs[j * PADQ + d0 + dd];
#pragma unroll
            for (int i = 0; i < 4; i++) {
                float p = Ps[(r0 + i) * PADP + j];
#pragma unroll
                for (int dd = 0; dd < 8; dd++) acc[i][dd] = fmaf(p, v[dd], acc[i][dd]);
            }
        }
        __syncthreads();  // before next tile overwrites Ks/Vs/Ps
    }

    // Epilogue: normalize and write ctx (B,T,C) with C-offset h*HD
#pragma unroll
    for (int i = 0; i < 4; i++) {
        float inv = 1.0f / l_i[i];
        int t = qbase + r0 + i;
        size_t base = (size_t)(b * Tt + t) * DIM + h * HD + d0;
#pragma unroll
        for (int dd = 0; dd < 8; dd++) ctx[base + dd] = acc[i][dd] * inv;
    }
}

// ---------------------------------------------------------------------------
// Launch
// ---------------------------------------------------------------------------
extern "C" void kernel_launch(void* const* d_in, const int* in_sizes, int n_in,
                              void* d_out, int out_size) {
    const float* x    = (const float*)d_in[0];
    const float* Wq   = (const float*)d_in[1];
    const float* Wkv  = (const float*)d_in[2];
    const float* Wo   = (const float*)d_in[3];
    const float* cosb = (const float*)d_in[4];
    const float* sinb = (const float*)d_in[5];
    float* out = (float*)d_out;

    float *qbuf, *kvbuf, *ctxbuf;
    cudaGetSymbolAddress((void**)&qbuf,  g_q);
    cudaGetSymbolAddress((void**)&kvbuf, g_kv);
    cudaGetSymbolAddress((void**)&ctxbuf, g_ctx);

    cudaFuncSetAttribute(flash_kernel, cudaFuncAttributeMaxDynamicSharedMemorySize,
                         FLASH_SMEM);

    const int M = Bb * Tt;  // 4096

    // q = x @ Wq   (4096 x 2048) @ (2048 x 2048)
    sgemm128<<<dim3(DIM / 128, M / 128), 256>>>(x, Wq, qbuf, M, DIM, DIM);
    // kv = x @ Wkv (4096 x 2048) @ (2048 x 1024)
    sgemm128<<<dim3((2 * KVH * HD) / 128, M / 128), 256>>>(x, Wkv, kvbuf, M,
                                                           2 * KVH * HD, DIM);
    // RoPE on q and k
    {
        int total = Bb * Tt * Hh * (HD / 2) + Bb * Tt * KVH * (HD / 2);
        int blocks = (total + 255) / 256;
        rope_kernel<<<blocks, 256>>>(qbuf, kvbuf, cosb, sinb);
    }
    // attention
    flash_kernel<<<dim3(Tt / 64, Hh, Bb), 256, FLASH_SMEM>>>(qbuf, kvbuf, ctxbuf);
    // out = ctx @ Wo
    sgemm128<<<dim3(DIM / 128, M / 128), 256>>>(ctxbuf, Wo, out, M, DIM, DIM);
}

// round 2
// speedup vs baseline: 1.5017x; 1.5017x over previous
#include <cuda_runtime.h>
#include <cuda_bf16.h>
#include <math.h>
#include <stdint.h>

// Problem constants
#define Bb   4
#define Tt   1024
#define DIM  2048
#define Hh   16
#define KVH  4
#define Gg   4
#define HD   128

#define MROWS (Bb * Tt)          // 4096
#define K3Q   (3 * DIM)          // 6144 (split-K layout)
#define NKV   (2 * KVH * HD)     // 1024

// fp32 scratch
__device__ float g_q  [MROWS * DIM];
__device__ float g_kv [MROWS * NKV];
__device__ float g_ctx[MROWS * DIM];

// bf16 split scratch: A-layouts are M x 3K with [hi | hi | lo] along K,
// B-layouts are 3K x N with [hi ; lo ; hi] along K  => A'B' = AhBh + AhBl + AlBh
__device__ __nv_bfloat16 g_xs  [MROWS * K3Q];
__device__ __nv_bfloat16 g_ctxs[MROWS * K3Q];
__device__ __nv_bfloat16 g_wqs [K3Q * DIM];
__device__ __nv_bfloat16 g_wkvs[K3Q * NKV];
__device__ __nv_bfloat16 g_wos [K3Q * DIM];

// ---------------------------------------------------------------------------
// PTX helpers
// ---------------------------------------------------------------------------
__device__ __forceinline__ void ldsm_x4(uint32_t& r0, uint32_t& r1,
                                        uint32_t& r2, uint32_t& r3, uint32_t addr) {
    asm volatile("ldmatrix.sync.aligned.m8n8.x4.shared.b16 {%0,%1,%2,%3}, [%4];\n"
                 : "=r"(r0), "=r"(r1), "=r"(r2), "=r"(r3) : "r"(addr));
}
__device__ __forceinline__ void ldsm_x4_t(uint32_t& r0, uint32_t& r1,
                                          uint32_t& r2, uint32_t& r3, uint32_t addr) {
    asm volatile("ldmatrix.sync.aligned.m8n8.x4.trans.shared.b16 {%0,%1,%2,%3}, [%4];\n"
                 : "=r"(r0), "=r"(r1), "=r"(r2), "=r"(r3) : "r"(addr));
}
__device__ __forceinline__ void mma_bf16(float* c, const uint32_t* a,
                                         uint32_t b0, uint32_t b1) {
    asm volatile(
        "mma.sync.aligned.m16n8k16.row.col.f32.bf16.bf16.f32 "
        "{%0,%1,%2,%3}, {%4,%5,%6,%7}, {%8,%9}, {%0,%1,%2,%3};\n"
        : "+f"(c[0]), "+f"(c[1]), "+f"(c[2]), "+f"(c[3])
        : "r"(a[0]), "r"(a[1]), "r"(a[2]), "r"(a[3]), "r"(b0), "r"(b1));
}
#define CP_ASYNC16(dst, src) \
    asm volatile("cp.async.cg.shared.global [%0], [%1], 16;\n" :: "r"(dst), "l"(src))
#define CP_COMMIT() asm volatile("cp.async.commit_group;\n" ::: "memory")
#define CP_WAIT0()  asm volatile("cp.async.wait_group 0;\n" ::: "memory")

// ---------------------------------------------------------------------------
// Split-conversion kernels (fp32 -> compensated bf16 pair layouts)
// ---------------------------------------------------------------------------
__global__ void conv_split_A(const float* __restrict__ in,
                             __nv_bfloat16* __restrict__ out, int M, int K) {
    int idx = blockIdx.x * blockDim.x + threadIdx.x;
    if (idx >= M * K) return;
    int m = idx / K, k = idx - m * K;
    float a = in[idx];
    __nv_bfloat16 hi = __float2bfloat16(a);
    __nv_bfloat16 lo = __float2bfloat16(a - __bfloat162float(hi));
    size_t base = (size_t)m * (3 * K);
    out[base + k]         = hi;
    out[base + K + k]     = hi;
    out[base + 2 * K + k] = lo;
}
__global__ void conv_split_B(const float* __restrict__ in,
                             __nv_bfloat16* __restrict__ out, int K, int N) {
    int idx = blockIdx.x * blockDim.x + threadIdx.x;
    if (idx >= K * N) return;
    int k = idx / N, n = idx - k * N;
    float a = in[idx];
    __nv_bfloat16 hi = __float2bfloat16(a);
    __nv_bfloat16 lo = __float2bfloat16(a - __bfloat162float(hi));
    out[(size_t)k * N + n]           = hi;   // pairs with Ah
    out[(size_t)(K + k) * N + n]     = lo;   // pairs with Ah
    out[(size_t)(2 * K + k) * N + n] = hi;   // pairs with Al
}

// ---------------------------------------------------------------------------
// bf16 tensor-core GEMM: C[M,N] fp32 = A[M,K3] bf16 @ B[K3,N] bf16
// 128x128 CTA tile, BK=32, 256 threads (8 warps: 2x4 of 64x32 warp tiles),
// cp.async double-buffered.
// ---------------------------------------------------------------------------
#define LDA 40    // halfs per A smem row (32 + 8 pad)
#define LDB 136   // halfs per B smem row (128 + 8 pad)

__global__ __launch_bounds__(256) void hgemm128(const __nv_bfloat16* __restrict__ A,
                                                const __nv_bfloat16* __restrict__ B,
                                                float* __restrict__ C,
                                                int M, int N, int K3) {
    __shared__ __nv_bfloat16 As[2][128 * LDA];
    __shared__ __nv_bfloat16 Bs[2][32 * LDB];

    const int tid  = threadIdx.x;
    const int lane = tid & 31;
    const int w    = tid >> 5;
    const int wm   = (w & 1) * 64;   // warp row offset
    const int wn   = (w >> 1) * 32;  // warp col offset
    const int rowBase = blockIdx.y * 128;
    const int colBase = blockIdx.x * 128;

    const uint32_t AsAddr = (uint32_t)__cvta_generic_to_shared(&As[0][0]);
    const uint32_t BsAddr = (uint32_t)__cvta_generic_to_shared(&Bs[0][0]);
    const uint32_t ASZ = 128 * LDA * 2;  // bytes per A stage
    const uint32_t BSZ = 32 * LDB * 2;

    float acc[4][4][4];
#pragma unroll
    for (int mi = 0; mi < 4; mi++)
#pragma unroll
        for (int ni = 0; ni < 4; ni++)
#pragma unroll
            for (int r = 0; r < 4; r++) acc[mi][ni][r] = 0.0f;

    const int NI = K3 / 32;

    // stage loader
    auto load_stage = [&](int it, int s) {
        int k0 = it * 32;
#pragma unroll
        for (int c = tid; c < 512; c += 256) {   // A: 128 rows x 4 chunks
            int row = c >> 2, cc = c & 3;
            const __nv_bfloat16* src = A + (size_t)(rowBase + row) * K3 + k0 + cc * 8;
            uint32_t dst = AsAddr + s * ASZ + (row * LDA + cc * 8) * 2;
            CP_ASYNC16(dst, src);
        }
#pragma unroll
        for (int c = tid; c < 512; c += 256) {   // B: 32 rows x 16 chunks
            int row = c >> 4, cc = c & 15;
            const __nv_bfloat16* src = B + (size_t)(k0 + row) * N + colBase + cc * 8;
            uint32_t dst = BsAddr + s * BSZ + (row * LDB + cc * 8) * 2;
            CP_ASYNC16(dst, src);
        }
        CP_COMMIT();
    };

    load_stage(0, 0);

    for (int it = 0; it < NI; ++it) {
        CP_WAIT0();
        __syncthreads();
        if (it + 1 < NI) load_stage(it + 1, (it + 1) & 1);

        const int s = it & 1;
        const uint32_t aBase = AsAddr + s * ASZ;
        const uint32_t bBase = BsAddr + s * BSZ;

#pragma unroll
        for (int ks = 0; ks < 32; ks += 16) {
            uint32_t ra[4][4];
#pragma unroll
            for (int mi = 0; mi < 4; mi++) {
                uint32_t addr = aBase +
                    ((wm + mi * 16 + (lane & 15)) * LDA + ks + (lane >> 4) * 8) * 2;
                ldsm_x4(ra[mi][0], ra[mi][1], ra[mi][2], ra[mi][3], addr);
            }
            uint32_t rb[2][4];
#pragma unroll
            for (int g = 0; g < 2; g++) {
                uint32_t addr = bBase +
                    ((ks + (lane & 15)) * LDB + wn + g * 16 + (lane >> 4) * 8) * 2;
                ldsm_x4_t(rb[g][0], rb[g][1], rb[g][2], rb[g][3], addr);
            }
#pragma unroll
            for (int mi = 0; mi < 4; mi++)
#pragma unroll
                for (int ni = 0; ni < 4; ni++)
                    mma_bf16(acc[mi][ni], ra[mi],
                             rb[ni >> 1][(ni & 1) * 2], rb[ni >> 1][(ni & 1) * 2 + 1]);
        }
        __syncthreads();
    }

    // epilogue
#pragma unroll
    for (int mi = 0; mi < 4; mi++)
#pragma unroll
        for (int ni = 0; ni < 4; ni++) {
            int r = rowBase + wm + mi * 16 + (lane >> 2);
            int cc = colBase + wn + ni * 8 + (lane & 3) * 2;
            *(float2*)&C[(size_t)r * N + cc] =
                make_float2(acc[mi][ni][0], acc[mi][ni][1]);
            *(float2*)&C[(size_t)(r + 8) * N + cc] =
                make_float2(acc[mi][ni][2], acc[mi][ni][3]);
        }
}

// ---------------------------------------------------------------------------
// RoPE applied in-place to q (B,T,H,HD) and k half of kv (B,T,2,KVH,HD)
// ---------------------------------------------------------------------------
__global__ void rope_kernel(float* __restrict__ q, float* __restrict__ kvb,
                            const float* __restrict__ cosb,
                            const float* __restrict__ sinb) {
    const int NQ = Bb * Tt * Hh * (HD / 2);
    const int NK = Bb * Tt * KVH * (HD / 2);
    int idx = blockIdx.x * blockDim.x + threadIdx.x;
    if (idx < NQ) {
        int d = idx & 63;
        int rest = idx >> 6;
        int h = rest & (Hh - 1); rest >>= 4;
        int t = rest & (Tt - 1);
        int b = rest >> 10;
        float c = cosb[t * 64 + d];
        float s = sinb[t * 64 + d];
        size_t base = ((size_t)(b * Tt + t) * Hh + h) * HD;
        float u1 = q[base + d];
        float u2 = q[base + 64 + d];
        q[base + d]      = u1 * c - u2 * s;
        q[base + 64 + d] = u1 * s + u2 * c;
    } else if (idx < NQ + NK) {
        int j = idx - NQ;
        int d = j & 63;
        int rest = j >> 6;
        int kvh = rest & (KVH - 1); rest >>= 2;
        int t = rest & (Tt - 1);
        int b = rest >> 10;
        float c = cosb[t * 64 + d];
        float s = sinb[t * 64 + d];
        size_t base = ((size_t)(b * Tt + t) * 2 + 0) * (KVH * HD) + kvh * HD;
        float u1 = kvb[base + d];
        float u2 = kvb[base + 64 + d];
        kvb[base + d]      = u1 * c - u2 * s;
        kvb[base + 64 + d] = u1 * s + u2 * c;
    }
}

// ---------------------------------------------------------------------------
// Flash-style causal attention with GQA (fp32, unchanged from R1)
// ---------------------------------------------------------------------------
#define PADQ 129
#define PADP 65
#define FLASH_SMEM ((3 * 64 * PADQ + 64 * PADP) * 4)

__global__ __launch_bounds__(256) void flash_kernel(const float* __restrict__ q,
                                                    const float* __restrict__ kvb,
                                                    float* __restrict__ ctx) {
    extern __shared__ float smem[];
    float* Qs = smem;
    float* Ks = Qs + 64 * PADQ;
    float* Vs = Ks + 64 * PADQ;
    float* Ps = Vs + 64 * PADQ;

    const int qtile = blockIdx.x;
    const int h     = blockIdx.y;
    const int b     = blockIdx.z;
    const int kvh   = h / Gg;
    const int qbase = qtile * 64;

    const int tid = threadIdx.x;
    const int tx = tid & 15;
    const int ty = tid >> 4;
    const int r0 = ty * 4;
    const int c0 = tx * 4;
    const int d0 = tx * 8;

    const float scale = 0.08838834764831845f;

    for (int idx = tid; idx < 64 * HD; idx += 256) {
        int r = idx >> 7, d = idx & 127;
        int t = qbase + r;
        Qs[r * PADQ + d] = q[((size_t)(b * Tt + t) * Hh + h) * HD + d] * scale;
    }

    float m_i[4], l_i[4], acc[4][8];
#pragma unroll
    for (int i = 0; i < 4; i++) {
        m_i[i] = -INFINITY;
        l_i[i] = 0.0f;
#pragma unroll
        for (int dd = 0; dd < 8; dd++) acc[i][dd] = 0.0f;
    }
    __syncthreads();

    const int ntiles = qtile + 1;
    for (int kt = 0; kt < ntiles; ++kt) {
        const int kbase = kt * 64;
        for (int idx = tid; idx < 64 * HD; idx += 256) {
            int r = idx >> 7, d = idx & 127;
            int t = kbase + r;
            size_t base = ((size_t)(b * Tt + t) * 2) * (KVH * HD) + kvh * HD + d;
            Ks[r * PADQ + d] = kvb[base];
            Vs[r * PADQ + d] = kvb[base + KVH * HD];
        }
        __syncthreads();

        float s[4][4];
#pragma unroll
        for (int i = 0; i < 4; i++)
#pragma unroll
            for (int j = 0; j < 4; j++) s[i][j] = 0.0f;
        for (int d = 0; d < HD; ++d) {
            float qa[4], kb[4];
#pragma unroll
            for (int i = 0; i < 4; i++) qa[i] = Qs[(r0 + i) * PADQ + d];
#pragma unroll
            for (int j = 0; j < 4; j++) kb[j] = Ks[(c0 + j) * PADQ + d];
#pragma unroll
            for (int i = 0; i < 4; i++)
#pragma unroll
                for (int j = 0; j < 4; j++) s[i][j] = fmaf(qa[i], kb[j], s[i][j]);
        }

        if (kt == qtile) {
#pragma unroll
            for (int i = 0; i < 4; i++)
#pragma unroll
                for (int j = 0; j < 4; j++)
                    if (kbase + c0 + j > qbase + r0 + i) s[i][j] = -INFINITY;
        }

#pragma unroll
        for (int i = 0; i < 4; i++) {
            float mx = fmaxf(fmaxf(s[i][0], s[i][1]), fmaxf(s[i][2], s[i][3]));
#pragma unroll
            for (int o = 1; o < 16; o <<= 1)
                mx = fmaxf(mx, __shfl_xor_sync(0xffffffffu, mx, o));
            float m_new = fmaxf(m_i[i], mx);
            float fac = __expf(m_i[i] - m_new);
            float rs = 0.0f;
#pragma unroll
            for (int j = 0; j < 4; j++) {
                float p = __expf(s[i][j] - m_new);
                s[i][j] = p;
                rs += p;
            }
#pragma unroll
            for (int o = 1; o < 16; o <<= 1)
                rs += __shfl_xor_sync(0xffffffffu, rs, o);
            l_i[i] = l_i[i] * fac + rs;
            m_i[i] = m_new;
#pragma unroll
            for (int dd = 0; dd < 8; dd++) acc[i][dd] *= fac;
#pragma unroll
            for (int j = 0; j < 4; j++) Ps[(r0 + i) * PADP + c0 + j] = s[i][j];
        }
        __syncthreads();

        for (int j = 0; j < 64; ++j) {
            float v[8];
#pragma unroll
            for (int dd = 0; dd < 8; dd++) v[dd] = Vs[j * PADQ + d0 + dd];
#pragma unroll
            for (int i = 0; i < 4; i++) {
                float p = Ps[(r0 + i) * PADP + j];
#pragma unroll
                for (int dd = 0; dd < 8; dd++) acc[i][dd] = fmaf(p, v[dd], acc[i][dd]);
            }
        }
        __syncthreads();
    }

#pragma unroll
    for (int i = 0; i < 4; i++) {
        float inv = 1.0f / l_i[i];
        int t = qbase + r0 + i;
        size_t base = (size_t)(b * Tt + t) * DIM + h * HD + d0;
#pragma unroll
        for (int dd = 0; dd < 8; dd++) ctx[base + dd] = acc[i][dd] * inv;
    }
}

// ---------------------------------------------------------------------------
// Launch
// ---------------------------------------------------------------------------
extern "C" void kernel_launch(void* const* d_in, const int* in_sizes, int n_in,
                              void* d_out, int out_size) {
    const float* x    = (const float*)d_in[0];
    const float* Wq   = (const float*)d_in[1];
    const float* Wkv  = (const float*)d_in[2];
    const float* Wo   = (const float*)d_in[3];
    const float* cosb = (const float*)d_in[4];
    const float* sinb = (const float*)d_in[5];
    float* out = (float*)d_out;

    float *qbuf, *kvbuf, *ctxbuf;
    __nv_bfloat16 *xs, *ctxs, *wqs, *wkvs, *wos;
    cudaGetSymbolAddress((void**)&qbuf,   g_q);
    cudaGetSymbolAddress((void**)&kvbuf,  g_kv);
    cudaGetSymbolAddress((void**)&ctxbuf, g_ctx);
    cudaGetSymbolAddress((void**)&xs,     g_xs);
    cudaGetSymbolAddress((void**)&ctxs,   g_ctxs);
    cudaGetSymbolAddress((void**)&wqs,    g_wqs);
    cudaGetSymbolAddress((void**)&wkvs,   g_wkvs);
    cudaGetSymbolAddress((void**)&wos,    g_wos);

    cudaFuncSetAttribute(flash_kernel, cudaFuncAttributeMaxDynamicSharedMemorySize,
                         FLASH_SMEM);

    const int M = MROWS;  // 4096

    // Split conversions
    conv_split_A<<<(M * DIM + 255) / 256, 256>>>(x, xs, M, DIM);
    conv_split_B<<<(DIM * DIM + 255) / 256, 256>>>(Wq, wqs, DIM, DIM);
    conv_split_B<<<(DIM * NKV + 255) / 256, 256>>>(Wkv, wkvs, DIM, NKV);
    conv_split_B<<<(DIM * DIM + 255) / 256, 256>>>(Wo, wos, DIM, DIM);

    // q = x @ Wq ; kv = x @ Wkv (tensor cores, compensated bf16)
    hgemm128<<<dim3(DIM / 128, M / 128), 256>>>(xs, wqs, qbuf, M, DIM, K3Q);
    hgemm128<<<dim3(NKV / 128, M / 128), 256>>>(xs, wkvs, kvbuf, M, NKV, K3Q);

    // RoPE
    {
        int total = Bb * Tt * Hh * (HD / 2) + Bb * Tt * KVH * (HD / 2);
        rope_kernel<<<(total + 255) / 256, 256>>>(qbuf, kvbuf, cosb, sinb);
    }

    // attention
    flash_kernel<<<dim3(Tt / 64, Hh, Bb), 256, FLASH_SMEM>>>(qbuf, kvbuf, ctxbuf);

    // out = ctx @ Wo
    conv_split_A<<<(M * DIM + 255) / 256, 256>>>(ctxbuf, ctxs, M, DIM);
    hgemm128<<<dim3(DIM / 128, M / 128), 256>>>(ctxs, wos, out, M, DIM, K3Q);
}

// round 3
// speedup vs baseline: 2.4936x; 1.6605x over previous
#include <cuda_runtime.h>
#include <cuda_bf16.h>
#include <math.h>
#include <stdint.h>

// Problem constants
#define Bb   4
#define Tt   1024
#define DIM  2048
#define Hh   16
#define KVH  4
#define Gg   4
#define HD   128

#define MROWS (Bb * Tt)          // 4096
#define K3Q   (3 * DIM)          // 6144 (split-K layout)
#define NKV   (2 * KVH * HD)     // 1024

// fp32 scratch
__device__ float g_q  [MROWS * DIM];
__device__ float g_kv [MROWS * NKV];
__device__ float g_ctx[MROWS * DIM];

// bf16 split scratch
__device__ __nv_bfloat16 g_xs  [MROWS * K3Q];
__device__ __nv_bfloat16 g_ctxs[MROWS * K3Q];
__device__ __nv_bfloat16 g_wqs [K3Q * DIM];
__device__ __nv_bfloat16 g_wkvs[K3Q * NKV];
__device__ __nv_bfloat16 g_wos [K3Q * DIM];

// ---------------------------------------------------------------------------
// PTX helpers
// ---------------------------------------------------------------------------
__device__ __forceinline__ void ldsm_x4(uint32_t& r0, uint32_t& r1,
                                        uint32_t& r2, uint32_t& r3, uint32_t addr) {
    asm volatile("ldmatrix.sync.aligned.m8n8.x4.shared.b16 {%0,%1,%2,%3}, [%4];\n"
                 : "=r"(r0), "=r"(r1), "=r"(r2), "=r"(r3) : "r"(addr));
}
__device__ __forceinline__ void ldsm_x4_t(uint32_t& r0, uint32_t& r1,
                                          uint32_t& r2, uint32_t& r3, uint32_t addr) {
    asm volatile("ldmatrix.sync.aligned.m8n8.x4.trans.shared.b16 {%0,%1,%2,%3}, [%4];\n"
                 : "=r"(r0), "=r"(r1), "=r"(r2), "=r"(r3) : "r"(addr));
}
__device__ __forceinline__ void mma_bf16(float* c, const uint32_t* a,
                                         uint32_t b0, uint32_t b1) {
    asm volatile(
        "mma.sync.aligned.m16n8k16.row.col.f32.bf16.bf16.f32 "
        "{%0,%1,%2,%3}, {%4,%5,%6,%7}, {%8,%9}, {%0,%1,%2,%3};\n"
        : "+f"(c[0]), "+f"(c[1]), "+f"(c[2]), "+f"(c[3])
        : "r"(a[0]), "r"(a[1]), "r"(a[2]), "r"(a[3]), "r"(b0), "r"(b1));
}
#define CP_ASYNC16(dst, src) \
    asm volatile("cp.async.cg.shared.global [%0], [%1], 16;\n" :: "r"(dst), "l"(src))
#define CP_COMMIT() asm volatile("cp.async.commit_group;\n" ::: "memory")
#define CP_WAIT1()  asm volatile("cp.async.wait_group 1;\n" ::: "memory")

__device__ __forceinline__ uint32_t packbf(float x, float y) {
    __nv_bfloat162 t = __floats2bfloat162_rn(x, y);
    return *(uint32_t*)&t;
}

// ---------------------------------------------------------------------------
// Split-conversion kernels
// ---------------------------------------------------------------------------
__global__ void conv_split_A(const float* __restrict__ in,
                             __nv_bfloat16* __restrict__ out, int M, int K) {
    int idx = blockIdx.x * blockDim.x + threadIdx.x;
    if (idx >= M * K) return;
    int m = idx / K, k = idx - m * K;
    float a = in[idx];
    __nv_bfloat16 hi = __float2bfloat16(a);
    __nv_bfloat16 lo = __float2bfloat16(a - __bfloat162float(hi));
    size_t base = (size_t)m * (3 * K);
    out[base + k]         = hi;
    out[base + K + k]     = hi;
    out[base + 2 * K + k] = lo;
}
__global__ void conv_split_B(const float* __restrict__ in,
                             __nv_bfloat16* __restrict__ out, int K, int N) {
    int idx = blockIdx.x * blockDim.x + threadIdx.x;
    if (idx >= K * N) return;
    int k = idx / N, n = idx - k * N;
    float a = in[idx];
    __nv_bfloat16 hi = __float2bfloat16(a);
    __nv_bfloat16 lo = __float2bfloat16(a - __bfloat162float(hi));
    out[(size_t)k * N + n]           = hi;
    out[(size_t)(K + k) * N + n]     = lo;
    out[(size_t)(2 * K + k) * N + n] = hi;
}

// ---------------------------------------------------------------------------
// bf16 TC GEMM: 128x256 CTA tile, BK=32, 3-stage cp.async, 8 warps (2m x 4n),
// warp tile 64x64.
// ---------------------------------------------------------------------------
#define LDA 40    // halfs per A smem row (32 + 8)
#define LDB 264   // halfs per B smem row (256 + 8)
#define GSTAGES 3
#define G_ASZ (128 * LDA * 2)  // bytes per A stage
#define G_BSZ (32 * LDB * 2)   // bytes per B stage
#define GEMM_SMEM (GSTAGES * (G_ASZ + G_BSZ))

__global__ __launch_bounds__(256, 1) void hgemm256(const __nv_bfloat16* __restrict__ A,
                                                   const __nv_bfloat16* __restrict__ B,
                                                   float* __restrict__ C,
                                                   int M, int N, int K3) {
    extern __shared__ __nv_bfloat16 gsm[];
    __nv_bfloat16* As = gsm;                          // GSTAGES x 128 x LDA
    __nv_bfloat16* Bs = gsm + GSTAGES * 128 * LDA;    // GSTAGES x 32 x LDB

    const int tid  = threadIdx.x;
    const int lane = tid & 31;
    const int w    = tid >> 5;
    const int wm   = (w & 1) * 64;
    const int wn   = (w >> 1) * 64;
    const int rowBase = blockIdx.y * 128;
    const int colBase = blockIdx.x * 256;

    const uint32_t AsAddr = (uint32_t)__cvta_generic_to_shared(As);
    const uint32_t BsAddr = (uint32_t)__cvta_generic_to_shared(Bs);

    float acc[4][8][4];
#pragma unroll
    for (int mi = 0; mi < 4; mi++)
#pragma unroll
        for (int ni = 0; ni < 8; ni++)
#pragma unroll
            for (int r = 0; r < 4; r++) acc[mi][ni][r] = 0.0f;

    const int NI = K3 / 32;

    auto load_stage = [&](int it, int s) {
        int k0 = it * 32;
#pragma unroll
        for (int c = 0; c < 2; c++) {               // A: 512 chunks of 16B
            int i = tid + c * 256;
            int row = i >> 2, cc = (i & 3) * 8;
            const __nv_bfloat16* src = A + (size_t)(rowBase + row) * K3 + k0 + cc;
            uint32_t dst = AsAddr + s * G_ASZ + (row * LDA + cc) * 2;
            CP_ASYNC16(dst, src);
        }
#pragma unroll
        for (int c = 0; c < 4; c++) {               // B: 1024 chunks of 16B
            int i = tid + c * 256;
            int row = i >> 5, cc = (i & 31) * 8;
            const __nv_bfloat16* src = B + (size_t)(k0 + row) * N + colBase + cc;
            uint32_t dst = BsAddr + s * G_BSZ + (row * LDB + cc) * 2;
            CP_ASYNC16(dst, src);
        }
        CP_COMMIT();
    };

    load_stage(0, 0);
    load_stage(1, 1);

    int s = 0;
    for (int it = 0; it < NI; ++it) {
        CP_WAIT1();
        __syncthreads();
        if (it + 2 < NI) {
            load_stage(it + 2, (it + 2) % GSTAGES);
        } else {
            CP_COMMIT();
        }

        const uint32_t aB = AsAddr + s * G_ASZ;
        const uint32_t bB = BsAddr + s * G_BSZ;

#pragma unroll
        for (int ks = 0; ks < 32; ks += 16) {
            uint32_t ra[4][4], rb[4][4];
#pragma unroll
            for (int mi = 0; mi < 4; mi++) {
                uint32_t addr = aB +
                    ((wm + mi * 16 + (lane & 15)) * LDA + ks + (lane >> 4) * 8) * 2;
                ldsm_x4(ra[mi][0], ra[mi][1], ra[mi][2], ra[mi][3], addr);
            }
#pragma unroll
            for (int g = 0; g < 4; g++) {
                uint32_t addr = bB +
                    ((ks + (lane & 15)) * LDB + wn + g * 16 + (lane >> 4) * 8) * 2;
                ldsm_x4_t(rb[g][0], rb[g][1], rb[g][2], rb[g][3], addr);
            }
#pragma unroll
            for (int mi = 0; mi < 4; mi++)
#pragma unroll
                for (int ni = 0; ni < 8; ni++)
                    mma_bf16(acc[mi][ni], ra[mi],
                             rb[ni >> 1][(ni & 1) * 2], rb[ni >> 1][(ni & 1) * 2 + 1]);
        }
        s = (s + 1) % GSTAGES;
    }

#pragma unroll
    for (int mi = 0; mi < 4; mi++)
#pragma unroll
        for (int ni = 0; ni < 8; ni++) {
            int r = rowBase + wm + mi * 16 + (lane >> 2);
            int cc = colBase + wn + ni * 8 + (lane & 3) * 2;
            *(float2*)&C[(size_t)r * N + cc] =
                make_float2(acc[mi][ni][0], acc[mi][ni][1]);
            *(float2*)&C[(size_t)(r + 8) * N + cc] =
                make_float2(acc[mi][ni][2], acc[mi][ni][3]);
        }
}

// ---------------------------------------------------------------------------
// RoPE (unchanged)
// ---------------------------------------------------------------------------
__global__ void rope_kernel(float* __restrict__ q, float* __restrict__ kvb,
                            const float* __restrict__ cosb,
                            const float* __restrict__ sinb) {
    const int NQ = Bb * Tt * Hh * (HD / 2);
    const int NK = Bb * Tt * KVH * (HD / 2);
    int idx = blockIdx.x * blockDim.x + threadIdx.x;
    if (idx < NQ) {
        int d = idx & 63;
        int rest = idx >> 6;
        int h = rest & (Hh - 1); rest >>= 4;
        int t = rest & (Tt - 1);
        int b = rest >> 10;
        float c = cosb[t * 64 + d];
        float s = sinb[t * 64 + d];
        size_t base = ((size_t)(b * Tt + t) * Hh + h) * HD;
        float u1 = q[base + d];
        float u2 = q[base + 64 + d];
        q[base + d]      = u1 * c - u2 * s;
        q[base + 64 + d] = u1 * s + u2 * c;
    } else if (idx < NQ + NK) {
        int j = idx - NQ;
        int d = j & 63;
        int rest = j >> 6;
        int kvh = rest & (KVH - 1); rest >>= 2;
        int t = rest & (Tt - 1);
        int b = rest >> 10;
        float c = cosb[t * 64 + d];
        float s = sinb[t * 64 + d];
        size_t base = ((size_t)(b * Tt + t) * 2 + 0) * (KVH * HD) + kvh * HD;
        float u1 = kvb[base + d];
        float u2 = kvb[base + 64 + d];
        kvb[base + d]      = u1 * c - u2 * s;
        kvb[base + 64 + d] = u1 * s + u2 * c;
    }
}

// ---------------------------------------------------------------------------
// Tensor-core flash attention (compensated bf16).
// CTA: 64 q rows of one (b,h). 128 threads = 4 warps, each warp 16 q rows.
// Smem rows are [hi(128) | lo(128)] bf16, LDH=264 halfs.
// ---------------------------------------------------------------------------
#define LDH 264
#define FLASH_SMEM (3 * 64 * LDH * 2)

__device__ __forceinline__ void split_store4(__nv_bfloat16* hi, __nv_bfloat16* lo,
                                             float4 v) {
    float a0 = v.x, a1 = v.y, a2 = v.z, a3 = v.w;
    __nv_bfloat16 h0 = __float2bfloat16(a0);
    __nv_bfloat16 h1 = __float2bfloat16(a1);
    __nv_bfloat16 h2 = __float2bfloat16(a2);
    __nv_bfloat16 h3 = __float2bfloat16(a3);
    *(__nv_bfloat162*)(hi)     = __nv_bfloat162(h0, h1);
    *(__nv_bfloat162*)(hi + 2) = __nv_bfloat162(h2, h3);
    *(__nv_bfloat162*)(lo)     = __nv_bfloat162(
        __float2bfloat16(a0 - __bfloat162float(h0)),
        __float2bfloat16(a1 - __bfloat162float(h1)));
    *(__nv_bfloat162*)(lo + 2) = __nv_bfloat162(
        __float2bfloat16(a2 - __bfloat162float(h2)),
        __float2bfloat16(a3 - __bfloat162float(h3)));
}

__global__ __launch_bounds__(128, 1) void flash_tc(const float* __restrict__ q,
                                                   const float* __restrict__ kvb,
                                                   float* __restrict__ ctx) {
    extern __shared__ __nv_bfloat16 fsm[];
    __nv_bfloat16* Qs = fsm;
    __nv_bfloat16* Ks = fsm + 64 * LDH;
    __nv_bfloat16* Vs = fsm + 2 * 64 * LDH;

    const int qtile = blockIdx.x;
    const int h     = blockIdx.y;
    const int b     = blockIdx.z;
    const int kvh   = h >> 2;
    const int qbase = qtile * 64;

    const int tid  = threadIdx.x;
    const int lane = tid & 31;
    const int w    = tid >> 5;
    const int gid  = lane >> 2;
    const int tig  = lane & 3;

    const uint32_t QsA = (uint32_t)__cvta_generic_to_shared(Qs);
    const uint32_t KsA = (uint32_t)__cvta_generic_to_shared(Ks);
    const uint32_t VsA = (uint32_t)__cvta_generic_to_shared(Vs);

    const float scale = 0.08838834764831845f;

    // Load + scale + split Q
    for (int i = tid; i < 64 * 32; i += 128) {
        int r = i >> 5, c4 = (i & 31) * 4;
        const float* src = q + ((size_t)(b * Tt + qbase + r) * Hh + h) * HD + c4;
        float4 v = *(const float4*)src;
        v.x *= scale; v.y *= scale; v.z *= scale; v.w *= scale;
        split_store4(Qs + r * LDH + c4, Qs + r * LDH + 128 + c4, v);
    }

    float oacc[16][4];
#pragma unroll
    for (int t = 0; t < 16; t++)
#pragma unroll
        for (int r = 0; r < 4; r++) oacc[t][r] = 0.0f;
    float m0 = -INFINITY, m1 = -INFINITY, l0 = 0.0f, l1 = 0.0f;

    for (int kt = 0; kt <= qtile; ++kt) {
        const int kbase = kt * 64;
        __syncthreads();
        // Load + split K, V
        for (int i = tid; i < 64 * 32; i += 128) {
            int r = i >> 5, c4 = (i & 31) * 4;
            size_t base = ((size_t)(b * Tt + kbase + r) * 2) * (KVH * HD)
                          + kvh * HD + c4;
            float4 kv4 = *(const float4*)&kvb[base];
            float4 vv4 = *(const float4*)&kvb[base + KVH * HD];
            split_store4(Ks + r * LDH + c4, Ks + r * LDH + 128 + c4, kv4);
            split_store4(Vs + r * LDH + c4, Vs + r * LDH + 128 + c4, vv4);
        }
        __syncthreads();

        // S = Qh Kh^T + Qh Kl^T + Ql Kh^T
        float sacc[8][4];
#pragma unroll
        for (int t = 0; t < 8; t++)
#pragma unroll
            for (int r = 0; r < 4; r++) sacc[t][r] = 0.0f;

#pragma unroll
        for (int kc = 0; kc < 8; kc++) {
            uint32_t qh[4], ql[4];
            uint32_t aaddr = QsA +
                ((w * 16 + (lane & 15)) * LDH + kc * 16 + (lane >> 4) * 8) * 2;
            ldsm_x4(qh[0], qh[1], qh[2], qh[3], aaddr);
            ldsm_x4(ql[0], ql[1], ql[2], ql[3], aaddr + 256);
#pragma unroll
            for (int g = 0; g < 4; g++) {
                uint32_t kh[4], kl[4];
                uint32_t baddr = KsA +
                    ((g * 16 + (lane & 15)) * LDH + kc * 16 + (lane >> 4) * 8) * 2;
                ldsm_x4(kh[0], kh[1], kh[2], kh[3], baddr);
                ldsm_x4(kl[0], kl[1], kl[2], kl[3], baddr + 256);
                mma_bf16(sacc[2 * g],     qh, kh[0], kh[2]);
                mma_bf16(sacc[2 * g + 1], qh, kh[1], kh[3]);
                mma_bf16(sacc[2 * g],     qh, kl[0], kl[2]);
                mma_bf16(sacc[2 * g + 1], qh, kl[1], kl[3]);
                mma_bf16(sacc[2 * g],     ql, kh[0], kh[2]);
                mma_bf16(sacc[2 * g + 1], ql, kh[1], kh[3]);
            }
        }

        // Causal mask on diagonal tile
        if (kt == qtile) {
            int row0 = w * 16 + gid;
#pragma unroll
            for (int s8 = 0; s8 < 8; s8++) {
                int cb = s8 * 8 + tig * 2;
                if (cb     > row0)     sacc[s8][0] = -INFINITY;
                if (cb + 1 > row0)     sacc[s8][1] = -INFINITY;
                if (cb     > row0 + 8) sacc[s8][2] = -INFINITY;
                if (cb + 1 > row0 + 8) sacc[s8][3] = -INFINITY;
            }
        }

        // Online softmax (rows gid and gid+8)
        float mx0 = -INFINITY, mx1 = -INFINITY;
#pragma unroll
        for (int s8 = 0; s8 < 8; s8++) {
            mx0 = fmaxf(mx0, fmaxf(sacc[s8][0], sacc[s8][1]));
            mx1 = fmaxf(mx1, fmaxf(sacc[s8][2], sacc[s8][3]));
        }
#pragma unroll
        for (int o = 1; o < 4; o <<= 1) {
            mx0 = fmaxf(mx0, __shfl_xor_sync(0xffffffffu, mx0, o));
            mx1 = fmaxf(mx1, __shfl_xor_sync(0xffffffffu, mx1, o));
        }
        float mn0 = fmaxf(m0, mx0), mn1 = fmaxf(m1, mx1);
        float f0 = __expf(m0 - mn0), f1 = __expf(m1 - mn1);
        float rs0 = 0.0f, rs1 = 0.0f;
#pragma unroll
        for (int s8 = 0; s8 < 8; s8++) {
            sacc[s8][0] = __expf(sacc[s8][0] - mn0);
            sacc[s8][1] = __expf(sacc[s8][1] - mn0);
            sacc[s8][2] = __expf(sacc[s8][2] - mn1);
            sacc[s8][3] = __expf(sacc[s8][3] - mn1);
            rs0 += sacc[s8][0] + sacc[s8][1];
            rs1 += sacc[s8][2] + sacc[s8][3];
        }
#pragma unroll
        for (int o = 1; o < 4; o <<= 1) {
            rs0 += __shfl_xor_sync(0xffffffffu, rs0, o);
            rs1 += __shfl_xor_sync(0xffffffffu, rs1, o);
        }
        l0 = l0 * f0 + rs0; m0 = mn0;
        l1 = l1 * f1 + rs1; m1 = mn1;
#pragma unroll
        for (int t = 0; t < 16; t++) {
            oacc[t][0] *= f0; oacc[t][1] *= f0;
            oacc[t][2] *= f1; oacc[t][3] *= f1;
        }

        // Repack P into A-fragments (hi + lo)
        uint32_t aPh[4][4], aPl[4][4];
#pragma unroll
        for (int j = 0; j < 4; j++) {
#pragma unroll
            for (int half = 0; half < 2; half++) {
                int t = 2 * j + half;
                float x0 = sacc[t][0], x1 = sacc[t][1];
                float x2 = sacc[t][2], x3 = sacc[t][3];
                __nv_bfloat16 h0 = __float2bfloat16(x0);
                __nv_bfloat16 h1 = __float2bfloat16(x1);
                __nv_bfloat16 h2 = __float2bfloat16(x2);
                __nv_bfloat16 h3 = __float2bfloat16(x3);
                __nv_bfloat162 ph01(h0, h1), ph23(h2, h3);
                aPh[j][2 * half]     = *(uint32_t*)&ph01;
                aPh[j][2 * half + 1] = *(uint32_t*)&ph23;
                __nv_bfloat162 pl01(__float2bfloat16(x0 - __bfloat162float(h0)),
                                    __float2bfloat16(x1 - __bfloat162float(h1)));
                __nv_bfloat162 pl23(__float2bfloat16(x2 - __bfloat162float(h2)),
                                    __float2bfloat16(x3 - __bfloat162float(h3)));
                aPl[j][2 * half]     = *(uint32_t*)&pl01;
                aPl[j][2 * half + 1] = *(uint32_t*)&pl23;
            }
        }

        // O += Ph Vh + Pl Vh + Ph Vl
#pragma unroll
        for (int j = 0; j < 4; j++) {
#pragma unroll
            for (int g = 0; g < 8; g++) {
                uint32_t vh[4], vl[4];
                uint32_t baddr = VsA +
                    ((j * 16 + (lane & 15)) * LDH + g * 16 + (lane >> 4) * 8) * 2;
                ldsm_x4_t(vh[0], vh[1], vh[2], vh[3], baddr);
                ldsm_x4_t(vl[0], vl[1], vl[2], vl[3], baddr + 256);
                mma_bf16(oacc[2 * g],     aPh[j], vh[0], vh[1]);
                mma_bf16(oacc[2 * g + 1], aPh[j], vh[2], vh[3]);
                mma_bf16(oacc[2 * g],     aPl[j], vh[0], vh[1]);
                mma_bf16(oacc[2 * g + 1], aPl[j], vh[2], vh[3]);
                mma_bf16(oacc[2 * g],     aPh[j], vl[0], vl[1]);
                mma_bf16(oacc[2 * g + 1], aPh[j], vl[2], vl[3]);
            }
        }
    }

    // Epilogue
    float inv0 = 1.0f / l0, inv1 = 1.0f / l1;
    int r0g = qbase + w * 16 + gid;
#pragma unroll
    for (int t = 0; t < 16; t++) {
        int dcol = t * 8 + tig * 2;
        size_t base0 = (size_t)(b * Tt + r0g) * DIM + h * HD + dcol;
        size_t base1 = (size_t)(b * Tt + r0g + 8) * DIM + h * HD + dcol;
        *(float2*)&ctx[base0] = make_float2(oacc[t][0] * inv0, oacc[t][1] * inv0);
        *(float2*)&ctx[base1] = make_float2(oacc[t][2] * inv1, oacc[t][3] * inv1);
    }
}

// ---------------------------------------------------------------------------
// Launch
// ---------------------------------------------------------------------------
extern "C" void kernel_launch(void* const* d_in, const int* in_sizes, int n_in,
                              void* d_out, int out_size) {
    const float* x    = (const float*)d_in[0];
    const float* Wq   = (const float*)d_in[1];
    const float* Wkv  = (const float*)d_in[2];
    const float* Wo   = (const float*)d_in[3];
    const float* cosb = (const float*)d_in[4];
    const float* sinb = (const float*)d_in[5];
    float* out = (float*)d_out;

    float *qbuf, *kvbuf, *ctxbuf;
    __nv_bfloat16 *xs, *ctxs, *wqs, *wkvs, *wos;
    cudaGetSymbolAddress((void**)&qbuf,   g_q);
    cudaGetSymbolAddress((void**)&kvbuf,  g_kv);
    cudaGetSymbolAddress((void**)&ctxbuf, g_ctx);
    cudaGetSymbolAddress((void**)&xs,     g_xs);
    cudaGetSymbolAddress((void**)&ctxs,   g_ctxs);
    cudaGetSymbolAddress((void**)&wqs,    g_wqs);
    cudaGetSymbolAddress((void**)&wkvs,   g_wkvs);
    cudaGetSymbolAddress((void**)&wos,    g_wos);

    cudaFuncSetAttribute(hgemm256, cudaFuncAttributeMaxDynamicSharedMemorySize,
                         GEMM_SMEM);
    cudaFuncSetAttribute(flash_tc, cudaFuncAttributeMaxDynamicSharedMemorySize,
                         FLASH_SMEM);

    const int M = MROWS;  // 4096

    // Split conversions
    conv_split_A<<<(M * DIM + 255) / 256, 256>>>(x, xs, M, DIM);
    conv_split_B<<<(DIM * DIM + 255) / 256, 256>>>(Wq, wqs, DIM, DIM);
    conv_split_B<<<(DIM * NKV + 255) / 256, 256>>>(Wkv, wkvs, DIM, NKV);
    conv_split_B<<<(DIM * DIM + 255) / 256, 256>>>(Wo, wos, DIM, DIM);

    // q = x @ Wq ; kv = x @ Wkv
    hgemm256<<<dim3(DIM / 256, M / 128), 256, GEMM_SMEM>>>(xs, wqs, qbuf, M, DIM, K3Q);
    hgemm256<<<dim3(NKV / 256, M / 128), 256, GEMM_SMEM>>>(xs, wkvs, kvbuf, M, NKV, K3Q);

    // RoPE
    {
        int total = Bb * Tt * Hh * (HD / 2) + Bb * Tt * KVH * (HD / 2);
        rope_kernel<<<(total + 255) / 256, 256>>>(qbuf, kvbuf, cosb, sinb);
    }

    // attention (tensor cores)
    flash_tc<<<dim3(Tt / 64, Hh, Bb), 128, FLASH_SMEM>>>(qbuf, kvbuf, ctxbuf);

    // out = ctx @ Wo
    conv_split_A<<<(M * DIM + 255) / 256, 256>>>(ctxbuf, ctxs, M, DIM);
    hgemm256<<<dim3(DIM / 256, M / 128), 256, GEMM_SMEM>>>(ctxs, wos, out, M, DIM, K3Q);
}

// round 7
// speedup vs baseline: 2.6354x; 1.0569x over previous
#include <cuda_runtime.h>
#include <cuda_bf16.h>
#include <math.h>
#include <stdint.h>

// Problem constants
#define Bb   4
#define Tt   1024
#define DIM  2048
#define Hh   16
#define KVH  4
#define Gg   4
#define HD   128

#define MROWS (Bb * Tt)          // 4096
#define K3Q   (3 * DIM)          // 6144 (split-K layout)
#define NKV   (2 * KVH * HD)     // 1024

// fp32 scratch
__device__ __align__(256) float g_q  [MROWS * DIM];
__device__ __align__(256) float g_kv [MROWS * NKV];
__device__ __align__(256) float g_ctx[MROWS * DIM];

// bf16 split scratch for GEMMs:
// A: [M, 3K] = [Ah | Ah | Al];  B: [3K, N] = [Bh ; Bl ; Bh]
__device__ __align__(256) __nv_bfloat16 g_xs  [MROWS * K3Q];
__device__ __align__(256) __nv_bfloat16 g_ctxs[MROWS * K3Q];
__device__ __align__(256) __nv_bfloat16 g_wqs [K3Q * DIM];
__device__ __align__(256) __nv_bfloat16 g_wkvs[K3Q * NKV];
__device__ __align__(256) __nv_bfloat16 g_wos [K3Q * DIM];

// pre-split attention operands (rope + scale applied):
// g_qs: (B,H,T, 256) halfs = [hi(128) | lo(128)]
// g_ks/g_vs: (B,KVH,T, 256) halfs
__device__ __align__(256) __nv_bfloat16 g_qs[Bb * Hh * Tt * 256];
__device__ __align__(256) __nv_bfloat16 g_ks[Bb * KVH * Tt * 256];
__device__ __align__(256) __nv_bfloat16 g_vs[Bb * KVH * Tt * 256];

// ---------------------------------------------------------------------------
// PTX helpers
// ---------------------------------------------------------------------------
__device__ __forceinline__ void ldsm_x4(uint32_t& r0, uint32_t& r1,
                                        uint32_t& r2, uint32_t& r3, uint32_t addr) {
    asm volatile("ldmatrix.sync.aligned.m8n8.x4.shared.b16 {%0,%1,%2,%3}, [%4];\n"
                 : "=r"(r0), "=r"(r1), "=r"(r2), "=r"(r3) : "r"(addr));
}
__device__ __forceinline__ void ldsm_x4_t(uint32_t& r0, uint32_t& r1,
                                          uint32_t& r2, uint32_t& r3, uint32_t addr) {
    asm volatile("ldmatrix.sync.aligned.m8n8.x4.trans.shared.b16 {%0,%1,%2,%3}, [%4];\n"
                 : "=r"(r0), "=r"(r1), "=r"(r2), "=r"(r3) : "r"(addr));
}
__device__ __forceinline__ void mma_bf16(float* c, const uint32_t* a,
                                         uint32_t b0, uint32_t b1) {
    asm volatile(
        "mma.sync.aligned.m16n8k16.row.col.f32.bf16.bf16.f32 "
        "{%0,%1,%2,%3}, {%4,%5,%6,%7}, {%8,%9}, {%0,%1,%2,%3};\n"
        : "+f"(c[0]), "+f"(c[1]), "+f"(c[2]), "+f"(c[3])
        : "r"(a[0]), "r"(a[1]), "r"(a[2]), "r"(a[3]), "r"(b0), "r"(b1));
}
#define CP_ASYNC16(dst, src) \
    asm volatile("cp.async.cg.shared.global [%0], [%1], 16;\n" :: "r"(dst), "l"(src))
#define CP_COMMIT() asm volatile("cp.async.commit_group;\n" ::: "memory")
template <int N>
__device__ __forceinline__ void cp_wait() {
    asm volatile("cp.async.wait_group %0;\n" :: "n"(N) : "memory");
}

// ---------------------------------------------------------------------------
// Split-conversion kernels
// ---------------------------------------------------------------------------
__global__ void conv_split_A(const float* __restrict__ in,
                             __nv_bfloat16* __restrict__ out, int M, int K) {
    int idx = blockIdx.x * blockDim.x + threadIdx.x;
    if (idx >= M * K) return;
    int m = idx / K, k = idx - m * K;
    float a = in[idx];
    __nv_bfloat16 hi = __float2bfloat16(a);
    __nv_bfloat16 lo = __float2bfloat16(a - __bfloat162float(hi));
    size_t base = (size_t)m * (3 * K);
    out[base + k]         = hi;
    out[base + K + k]     = hi;
    out[base + 2 * K + k] = lo;
}
__global__ void conv_split_B(const float* __restrict__ in,
                             __nv_bfloat16* __restrict__ out, int K, int N) {
    int idx = blockIdx.x * blockDim.x + threadIdx.x;
    if (idx >= K * N) return;
    int k = idx / N, n = idx - k * N;
    float a = in[idx];
    __nv_bfloat16 hi = __float2bfloat16(a);
    __nv_bfloat16 lo = __float2bfloat16(a - __bfloat162float(hi));
    out[(size_t)k * N + n]           = hi;
    out[(size_t)(K + k) * N + n]     = lo;
    out[(size_t)(2 * K + k) * N + n] = hi;
}

// ---------------------------------------------------------------------------
// bf16 TC GEMM: 128x256 CTA tile, BK=32, 4-stage cp.async (wait_group 2),
// 8 warps (2m x 4n), warp tile 64x64.
// ---------------------------------------------------------------------------
#define LDA 40    // halfs per A smem row (32 + 8)
#define LDB 264   // halfs per B smem row (256 + 8)
#define GSTAGES 4
#define G_ASZ (128 * LDA * 2)
#define G_BSZ (32 * LDB * 2)
#define G_STG (G_ASZ + G_BSZ)
#define GEMM_SMEM (GSTAGES * G_STG)

__global__ __launch_bounds__(256, 1) void hgemm256(const __nv_bfloat16* __restrict__ A,
                                                   const __nv_bfloat16* __restrict__ B,
                                                   float* __restrict__ C,
                                                   int M, int N, int K3) {
    extern __shared__ __nv_bfloat16 gsm[];

    const int tid  = threadIdx.x;
    const int lane = tid & 31;
    const int w    = tid >> 5;
    const int wm   = (w & 1) * 64;
    const int wn   = (w >> 1) * 64;
    const int rowBase = blockIdx.y * 128;
    const int colBase = blockIdx.x * 256;

    const uint32_t S0 = (uint32_t)__cvta_generic_to_shared(gsm);

    float acc[4][8][4];
#pragma unroll
    for (int mi = 0; mi < 4; mi++)
#pragma unroll
        for (int ni = 0; ni < 8; ni++)
#pragma unroll
            for (int r = 0; r < 4; r++) acc[mi][ni][r] = 0.0f;

    const int NI = K3 / 32;

    auto load_stage = [&](int it, int s) {
        int k0 = it * 32;
        const uint32_t aB = S0 + s * G_STG;
        const uint32_t bB = aB + G_ASZ;
#pragma unroll
        for (int c = 0; c < 2; c++) {               // A: 512 chunks of 16B
            int i = tid + c * 256;
            int row = i >> 2, cc = (i & 3) * 8;
            const __nv_bfloat16* src = A + (size_t)(rowBase + row) * K3 + k0 + cc;
            CP_ASYNC16(aB + (row * LDA + cc) * 2, src);
        }
#pragma unroll
        for (int c = 0; c < 4; c++) {               // B: 1024 chunks of 16B
            int i = tid + c * 256;
            int row = i >> 5, cc = (i & 31) * 8;
            const __nv_bfloat16* src = B + (size_t)(k0 + row) * N + colBase + cc;
            CP_ASYNC16(bB + (row * LDB + cc) * 2, src);
        }
        CP_COMMIT();
    };

    load_stage(0, 0);
    load_stage(1, 1);
    load_stage(2, 2);

    for (int it = 0; it < NI; ++it) {
        cp_wait<2>();
        __syncthreads();
        if (it + 3 < NI) load_stage(it + 3, (it + 3) & 3);
        else CP_COMMIT();

        const int s = it & 3;
        const uint32_t aB = S0 + s * G_STG;
        const uint32_t bB = aB + G_ASZ;

#pragma unroll
        for (int ks = 0; ks < 32; ks += 16) {
            uint32_t ra[4][4], rb[4][4];
#pragma unroll
            for (int mi = 0; mi < 4; mi++) {
                uint32_t addr = aB +
                    ((wm + mi * 16 + (lane & 15)) * LDA + ks + (lane >> 4) * 8) * 2;
                ldsm_x4(ra[mi][0], ra[mi][1], ra[mi][2], ra[mi][3], addr);
            }
#pragma unroll
            for (int g = 0; g < 4; g++) {
                uint32_t addr = bB +
                    ((ks + (lane & 15)) * LDB + wn + g * 16 + (lane >> 4) * 8) * 2;
                ldsm_x4_t(rb[g][0], rb[g][1], rb[g][2], rb[g][3], addr);
            }
#pragma unroll
            for (int mi = 0; mi < 4; mi++)
#pragma unroll
                for (int ni = 0; ni < 8; ni++)
                    mma_bf16(acc[mi][ni], ra[mi],
                             rb[ni >> 1][(ni & 1) * 2], rb[ni >> 1][(ni & 1) * 2 + 1]);
        }
    }

#pragma unroll
    for (int mi = 0; mi < 4; mi++)
#pragma unroll
        for (int ni = 0; ni < 8; ni++) {
            int r = rowBase + wm + mi * 16 + (lane >> 2);
            int cc = colBase + wn + ni * 8 + (lane & 3) * 2;
            *(float2*)&C[(size_t)r * N + cc] =
                make_float2(acc[mi][ni][0], acc[mi][ni][1]);
            *(float2*)&C[(size_t)(r + 8) * N + cc] =
                make_float2(acc[mi][ni][2], acc[mi][ni][3]);
        }
}

// ---------------------------------------------------------------------------
// Fused prep: RoPE + scale + compensated split + head-major relayout.
// ---------------------------------------------------------------------------
__global__ void prep_kernel(const float* __restrict__ q,
                            const float* __restrict__ kvb,
                            const float* __restrict__ cosb,
                            const float* __restrict__ sinb,
                            __nv_bfloat16* __restrict__ qs,
                            __nv_bfloat16* __restrict__ ks,
                            __nv_bfloat16* __restrict__ vs) {
    const int NQ = Bb * Tt * Hh * 64;
    const int NK = Bb * Tt * KVH * 64;
    const int NV = Bb * Tt * KVH * 128;
    const float scale = 0.08838834764831845f;
    int idx = blockIdx.x * blockDim.x + threadIdx.x;
    if (idx < NQ) {
        int d = idx & 63;
        int h = (idx >> 6) & 15;
        int t = (idx >> 10) & 1023;
        int b = idx >> 20;
        float c = cosb[t * 64 + d];
        float s = sinb[t * 64 + d];
        size_t src = ((size_t)(b * Tt + t) * Hh + h) * HD;
        float u1 = q[src + d], u2 = q[src + 64 + d];
        float r1 = (u1 * c - u2 * s) * scale;
        float r2 = (u1 * s + u2 * c) * scale;
        __nv_bfloat16 h1 = __float2bfloat16(r1);
        __nv_bfloat16 h2 = __float2bfloat16(r2);
        size_t dst = ((size_t)(b * Hh + h) * Tt + t) * 256;
        qs[dst + d]        = h1;
        qs[dst + 128 + d]  = __float2bfloat16(r1 - __bfloat162float(h1));
        qs[dst + 64 + d]   = h2;
        qs[dst + 192 + d]  = __float2bfloat16(r2 - __bfloat162float(h2));
    } else if (idx < NQ + NK) {
        int j = idx - NQ;
        int d = j & 63;
        int kvh = (j >> 6) & 3;
        int t = (j >> 8) & 1023;
        int b = j >> 18;
        float c = cosb[t * 64 + d];
        float s = sinb[t * 64 + d];
        size_t src = ((size_t)(b * Tt + t) * 2) * (KVH * HD) + kvh * HD;
        float u1 = kvb[src + d], u2 = kvb[src + 64 + d];
        float r1 = u1 * c - u2 * s;
        float r2 = u1 * s + u2 * c;
        __nv_bfloat16 h1 = __float2bfloat16(r1);
        __nv_bfloat16 h2 = __float2bfloat16(r2);
        size_t dst = ((size_t)(b * KVH + kvh) * Tt + t) * 256;
        ks[dst + d]        = h1;
        ks[dst + 128 + d]  = __float2bfloat16(r1 - __bfloat162float(h1));
        ks[dst + 64 + d]   = h2;
        ks[dst + 192 + d]  = __float2bfloat16(r2 - __bfloat162float(h2));
    } else if (idx < NQ + NK + NV) {
        int j = idx - NQ - NK;
        int d = j & 127;
        int kvh = (j >> 7) & 3;
        int t = (j >> 9) & 1023;
        int b = j >> 19;
        size_t src = ((size_t)(b * Tt + t) * 2 + 1) * (KVH * HD) + kvh * HD;
        float u = kvb[src + d];
        __nv_bfloat16 hh = __float2bfloat16(u);
        size_t dst = ((size_t)(b * KVH + kvh) * Tt + t) * 256;
        vs[dst + d]       = hh;
        vs[dst + 128 + d] = __float2bfloat16(u - __bfloat162float(hh));
    }
}

// ---------------------------------------------------------------------------
// Tensor-core flash attention, pre-split operands, cp.async double-buffered K/V.
// CTA: 64 q rows of one (b,h). 128 threads = 4 warps.
// ---------------------------------------------------------------------------
#define LDH 264
#define F_QSZ (64 * LDH * 2)
#define F_STG (64 * LDH * 2)
#define FLASH_SMEM (F_QSZ + 4 * F_STG)   // Q + 2xK + 2xV

__global__ __launch_bounds__(128, 1) void flash_tc(const __nv_bfloat16* __restrict__ qs,
                                                   const __nv_bfloat16* __restrict__ ks,
                                                   const __nv_bfloat16* __restrict__ vs,
                                                   float* __restrict__ ctx) {
    extern __shared__ __nv_bfloat16 fsm[];

    const int qtile = blockIdx.x;
    const int h     = blockIdx.y;
    const int b     = blockIdx.z;
    const int kvh   = h >> 2;
    const int qbase = qtile * 64;

    const int tid  = threadIdx.x;
    const int lane = tid & 31;
    const int w    = tid >> 5;
    const int gid  = lane >> 2;
    const int tig  = lane & 3;

    const uint32_t QsA = (uint32_t)__cvta_generic_to_shared(fsm);
    const uint32_t KsA = QsA + F_QSZ;
    const uint32_t VsA = KsA + 2 * F_STG;

    // Q load: 64 rows x 32 chunks of 16B = 2048 chunks, 16 per thread
    {
        const __nv_bfloat16* qsrc = qs + ((size_t)(b * Hh + h) * Tt + qbase) * 256;
#pragma unroll
        for (int i = 0; i < 16; i++) {
            int c = tid + i * 128;
            int r = c >> 5, cc = (c & 31) * 8;
            CP_ASYNC16(QsA + (r * LDH + cc) * 2, qsrc + r * 256 + cc);
        }
        CP_COMMIT();
    }

    auto load_kv = [&](int kt, int s) {
        const __nv_bfloat16* kb = ks + ((size_t)(b * KVH + kvh) * Tt + kt * 64) * 256;
        const __nv_bfloat16* vb = vs + ((size_t)(b * KVH + kvh) * Tt + kt * 64) * 256;
        const uint32_t kd = KsA + s * F_STG;
        const uint32_t vd = VsA + s * F_STG;
#pragma unroll
        for (int i = 0; i < 16; i++) {
            int c = tid + i * 128;
            int r = c >> 5, cc = (c & 31) * 8;
            CP_ASYNC16(kd + (r * LDH + cc) * 2, kb + r * 256 + cc);
        }
#pragma unroll
        for (int i = 0; i < 16; i++) {
            int c = tid + i * 128;
            int r = c >> 5, cc = (c & 31) * 8;
            CP_ASYNC16(vd + (r * LDH + cc) * 2, vb + r * 256 + cc);
        }
        CP_COMMIT();
    };

    load_kv(0, 0);

    float oacc[16][4];
#pragma unroll
    for (int t = 0; t < 16; t++)
#pragma unroll
        for (int r = 0; r < 4; r++) oacc[t][r] = 0.0f;
    float m0 = -INFINITY, m1 = -INFINITY, l0 = 0.0f, l1 = 0.0f;

    for (int kt = 0; kt <= qtile; ++kt) {
        if (kt < qtile) load_kv(kt + 1, (kt + 1) & 1);
        else CP_COMMIT();
        cp_wait<1>();
        __syncthreads();

        const uint32_t kB = KsA + (kt & 1) * F_STG;
        const uint32_t vB = VsA + (kt & 1) * F_STG;

        // S = Qh Kh^T + Qh Kl^T + Ql Kh^T
        float sacc[8][4];
#pragma unroll
        for (int t = 0; t < 8; t++)
#pragma unroll
            for (int r = 0; r < 4; r++) sacc[t][r] = 0.0f;

#pragma unroll
        for (int kc = 0; kc < 8; kc++) {
            uint32_t qh[4], ql[4];
            uint32_t aaddr = QsA +
                ((w * 16 + (lane & 15)) * LDH + kc * 16 + (lane >> 4) * 8) * 2;
            ldsm_x4(qh[0], qh[1], qh[2], qh[3], aaddr);
            ldsm_x4(ql[0], ql[1], ql[2], ql[3], aaddr + 256);
#pragma unroll
            for (int g = 0; g < 4; g++) {
                uint32_t kh[4], kl[4];
                uint32_t baddr = kB +
                    ((g * 16 + (lane & 15)) * LDH + kc * 16 + (lane >> 4) * 8) * 2;
                ldsm_x4(kh[0], kh[1], kh[2], kh[3], baddr);
                ldsm_x4(kl[0], kl[1], kl[2], kl[3], baddr + 256);
                mma_bf16(sacc[2 * g],     qh, kh[0], kh[2]);
                mma_bf16(sacc[2 * g + 1], qh, kh[1], kh[3]);
                mma_bf16(sacc[2 * g],     qh, kl[0], kl[2]);
                mma_bf16(sacc[2 * g + 1], qh, kl[1], kl[3]);
                mma_bf16(sacc[2 * g],     ql, kh[0], kh[2]);
                mma_bf16(sacc[2 * g + 1], ql, kh[1], kh[3]);
            }
        }

        if (kt == qtile) {
            int row0 = w * 16 + gid;
#pragma unroll
            for (int s8 = 0; s8 < 8; s8++) {
                int cb = s8 * 8 + tig * 2;
                if (cb     > row0)     sacc[s8][0] = -INFINITY;
                if (cb + 1 > row0)     sacc[s8][1] = -INFINITY;
                if (cb     > row0 + 8) sacc[s8][2] = -INFINITY;
                if (cb + 1 > row0 + 8) sacc[s8][3] = -INFINITY;
            }
        }

        float mx0 = -INFINITY, mx1 = -INFINITY;
#pragma unroll
        for (int s8 = 0; s8 < 8; s8++) {
            mx0 = fmaxf(mx0, fmaxf(sacc[s8][0], sacc[s8][1]));
            mx1 = fmaxf(mx1, fmaxf(sacc[s8][2], sacc[s8][3]));
        }
#pragma unroll
        for (int o = 1; o < 4; o <<= 1) {
            mx0 = fmaxf(mx0, __shfl_xor_sync(0xffffffffu, mx0, o));
            mx1 = fmaxf(mx1, __shfl_xor_sync(0xffffffffu, mx1, o));
        }
        float mn0 = fmaxf(m0, mx0), mn1 = fmaxf(m1, mx1);
        float f0 = __expf(m0 - mn0), f1 = __expf(m1 - mn1);
        float rs0 = 0.0f, rs1 = 0.0f;
#pragma unroll
        for (int s8 = 0; s8 < 8; s8++) {
            sacc[s8][0] = __expf(sacc[s8][0] - mn0);
            sacc[s8][1] = __expf(sacc[s8][1] - mn0);
            sacc[s8][2] = __expf(sacc[s8][2] - mn1);
            sacc[s8][3] = __expf(sacc[s8][3] - mn1);
            rs0 += sacc[s8][0] + sacc[s8][1];
            rs1 += sacc[s8][2] + sacc[s8][3];
        }
#pragma unroll
        for (int o = 1; o < 4; o <<= 1) {
            rs0 += __shfl_xor_sync(0xffffffffu, rs0, o);
            rs1 += __shfl_xor_sync(0xffffffffu, rs1, o);
        }
        l0 = l0 * f0 + rs0; m0 = mn0;
        l1 = l1 * f1 + rs1; m1 = mn1;
#pragma unroll
        for (int t = 0; t < 16; t++) {
            oacc[t][0] *= f0; oacc[t][1] *= f0;
            oacc[t][2] *= f1; oacc[t][3] *= f1;
        }

        // Repack P (hi + lo)
        uint32_t aPh[4][4], aPl[4][4];
#pragma unroll
        for (int j = 0; j < 4; j++) {
#pragma unroll
            for (int half = 0; half < 2; half++) {
                int t = 2 * j + half;
                float x0 = sacc[t][0], x1 = sacc[t][1];
                float x2 = sacc[t][2], x3 = sacc[t][3];
                __nv_bfloat16 h0 = __float2bfloat16(x0);
                __nv_bfloat16 h1 = __float2bfloat16(x1);
                __nv_bfloat16 h2 = __float2bfloat16(x2);
                __nv_bfloat16 h3 = __float2bfloat16(x3);
                __nv_bfloat162 ph01(h0, h1), ph23(h2, h3);
                aPh[j][2 * half]     = *(uint32_t*)&ph01;
                aPh[j][2 * half + 1] = *(uint32_t*)&ph23;
                __nv_bfloat162 pl01(__float2bfloat16(x0 - __bfloat162float(h0)),
                                    __float2bfloat16(x1 - __bfloat162float(h1)));
                __nv_bfloat162 pl23(__float2bfloat16(x2 - __bfloat162float(h2)),
                                    __float2bfloat16(x3 - __bfloat162float(h3)));
                aPl[j][2 * half]     = *(uint32_t*)&pl01;
                aPl[j][2 * half + 1] = *(uint32_t*)&pl23;
            }
        }

        // O += Ph Vh + Pl Vh + Ph Vl
#pragma unroll
        for (int j = 0; j < 4; j++) {
#pragma unroll
            for (int g = 0; g < 8; g++) {
                uint32_t vh[4], vl[4];
                uint32_t baddr = vB +
                    ((j * 16 + (lane & 15)) * LDH + g * 16 + (lane >> 4) * 8) * 2;
                ldsm_x4_t(vh[0], vh[1], vh[2], vh[3], baddr);
                ldsm_x4_t(vl[0], vl[1], vl[2], vl[3], baddr + 256);
                mma_bf16(oacc[2 * g],     aPh[j], vh[0], vh[1]);
                mma_bf16(oacc[2 * g + 1], aPh[j], vh[2], vh[3]);
                mma_bf16(oacc[2 * g],     aPl[j], vh[0], vh[1]);
                mma_bf16(oacc[2 * g + 1], aPl[j], vh[2], vh[3]);
                mma_bf16(oacc[2 * g],     aPh[j], vl[0], vl[1]);
                mma_bf16(oacc[2 * g + 1], aPh[j], vl[2], vl[3]);
            }
        }
        __syncthreads();   // protect stage reuse by next iteration's load
    }

    float inv0 = 1.0f / l0, inv1 = 1.0f / l1;
    int r0g = qbase + w * 16 + gid;
#pragma unroll
    for (int t = 0; t < 16; t++) {
        int dcol = t * 8 + tig * 2;
        size_t base0 = (size_t)(b * Tt + r0g) * DIM + h * HD + dcol;
        size_t base1 = (size_t)(b * Tt + r0g + 8) * DIM + h * HD + dcol;
        *(float2*)&ctx[base0] = make_float2(oacc[t][0] * inv0, oacc[t][1] * inv0);
        *(float2*)&ctx[base1] = make_float2(oacc[t][2] * inv1, oacc[t][3] * inv1);
    }
}

// ---------------------------------------------------------------------------
// Launch
// ---------------------------------------------------------------------------
extern "C" void kernel_launch(void* const* d_in, const int* in_sizes, int n_in,
                              void* d_out, int out_size) {
    const float* x    = (const float*)d_in[0];
    const float* Wq   = (const float*)d_in[1];
    const float* Wkv  = (const float*)d_in[2];
    const float* Wo   = (const float*)d_in[3];
    const float* cosb = (const float*)d_in[4];
    const float* sinb = (const float*)d_in[5];
    float* out = (float*)d_out;

    float *qbuf, *kvbuf, *ctxbuf;
    __nv_bfloat16 *xs, *ctxs, *wqs, *wkvs, *wos, *qsb, *ksb, *vsb;
    cudaGetSymbolAddress((void**)&qbuf,   g_q);
    cudaGetSymbolAddress((void**)&kvbuf,  g_kv);
    cudaGetSymbolAddress((void**)&ctxbuf, g_ctx);
    cudaGetSymbolAddress((void**)&xs,     g_xs);
    cudaGetSymbolAddress((void**)&ctxs,   g_ctxs);
    cudaGetSymbolAddress((void**)&wqs,    g_wqs);
    cudaGetSymbolAddress((void**)&wkvs,   g_wkvs);
    cudaGetSymbolAddress((void**)&wos,    g_wos);
    cudaGetSymbolAddress((void**)&qsb,    g_qs);
    cudaGetSymbolAddress((void**)&ksb,    g_ks);
    cudaGetSymbolAddress((void**)&vsb,    g_vs);

    cudaFuncSetAttribute(hgemm256, cudaFuncAttributeMaxDynamicSharedMemorySize,
                         GEMM_SMEM);
    cudaFuncSetAttribute(flash_tc, cudaFuncAttributeMaxDynamicSharedMemorySize,
                         FLASH_SMEM);

    const int M = MROWS;  // 4096

    // Split conversions
    conv_split_A<<<(M * DIM + 255) / 256, 256>>>(x, xs, M, DIM);
    conv_split_B<<<(DIM * DIM + 255) / 256, 256>>>(Wq, wqs, DIM, DIM);
    conv_split_B<<<(DIM * NKV + 255) / 256, 256>>>(Wkv, wkvs, DIM, NKV);
    conv_split_B<<<(DIM * DIM + 255) / 256, 256>>>(Wo, wos, DIM, DIM);

    // q = x @ Wq ; kv = x @ Wkv
    hgemm256<<<dim3(DIM / 256, M / 128), 256, GEMM_SMEM>>>(xs, wqs, qbuf, M, DIM, K3Q);
    hgemm256<<<dim3(NKV / 256, M / 128), 256, GEMM_SMEM>>>(xs, wkvs, kvbuf, M, NKV, K3Q);

    // fused rope + split + relayout
    {
        int total = Bb * Tt * Hh * 64 + Bb * Tt * KVH * 64 + Bb * Tt * KVH * 128;
        prep_kernel<<<(total + 255) / 256, 256>>>(qbuf, kvbuf, cosb, sinb,
                                                  qsb, ksb, vsb);
    }

    // attention
    flash_tc<<<dim3(Tt / 64, Hh, Bb), 128, FLASH_SMEM>>>(qsb, ksb, vsb, ctxbuf);

    // out = ctx @ Wo
    conv_split_A<<<(M * DIM + 255) / 256, 256>>>(ctxbuf, ctxs, M, DIM);
    hgemm256<<<dim3(DIM / 256, M / 128), 256, GEMM_SMEM>>>(ctxs, wos, out, M, DIM, K3Q);
}

// round 8
// speedup vs baseline: 3.4868x; 1.3231x over previous
#include <cuda_runtime.h>
#include <cuda_bf16.h>
#include <cuda_fp16.h>
#include <math.h>
#include <stdint.h>

// Problem constants
#define Bb   4
#define Tt   1024
#define DIM  2048
#define Hh   16
#define KVH  4
#define Gg   4
#define HD   128

#define MROWS (Bb * Tt)          // 4096
#define K2Q   (2 * DIM)          // 4096 (fp16 2-term split-K layout)
#define NKV   (2 * KVH * HD)     // 1024

// fp32 scratch
__device__ __align__(256) float g_q  [MROWS * DIM];
__device__ __align__(256) float g_kv [MROWS * NKV];
__device__ __align__(256) float g_ctx[MROWS * DIM];

// fp16 split scratch for GEMMs:
// A: [M, 2K] = [Ah | Al];  B: [2K, N] = [Bh ; Bh]  =>  A'.B' = (Ah+Al).Bh = A.Bh
__device__ __align__(256) __half g_xs  [MROWS * K2Q];
__device__ __align__(256) __half g_ctxs[MROWS * K2Q];
__device__ __align__(256) __half g_wqs [K2Q * DIM];
__device__ __align__(256) __half g_wkvs[K2Q * NKV];
__device__ __align__(256) __half g_wos [K2Q * DIM];

// pre-split attention operands (rope + scale applied), bf16 3-term path:
__device__ __align__(256) __nv_bfloat16 g_qs[Bb * Hh * Tt * 256];
__device__ __align__(256) __nv_bfloat16 g_ks[Bb * KVH * Tt * 256];
__device__ __align__(256) __nv_bfloat16 g_vs[Bb * KVH * Tt * 256];

// ---------------------------------------------------------------------------
// PTX helpers
// ---------------------------------------------------------------------------
__device__ __forceinline__ void ldsm_x4(uint32_t& r0, uint32_t& r1,
                                        uint32_t& r2, uint32_t& r3, uint32_t addr) {
    asm volatile("ldmatrix.sync.aligned.m8n8.x4.shared.b16 {%0,%1,%2,%3}, [%4];\n"
                 : "=r"(r0), "=r"(r1), "=r"(r2), "=r"(r3) : "r"(addr));
}
__device__ __forceinline__ void ldsm_x4_t(uint32_t& r0, uint32_t& r1,
                                          uint32_t& r2, uint32_t& r3, uint32_t addr) {
    asm volatile("ldmatrix.sync.aligned.m8n8.x4.trans.shared.b16 {%0,%1,%2,%3}, [%4];\n"
                 : "=r"(r0), "=r"(r1), "=r"(r2), "=r"(r3) : "r"(addr));
}
__device__ __forceinline__ void mma_bf16(float* c, const uint32_t* a,
                                         uint32_t b0, uint32_t b1) {
    asm volatile(
        "mma.sync.aligned.m16n8k16.row.col.f32.bf16.bf16.f32 "
        "{%0,%1,%2,%3}, {%4,%5,%6,%7}, {%8,%9}, {%0,%1,%2,%3};\n"
        : "+f"(c[0]), "+f"(c[1]), "+f"(c[2]), "+f"(c[3])
        : "r"(a[0]), "r"(a[1]), "r"(a[2]), "r"(a[3]), "r"(b0), "r"(b1));
}
__device__ __forceinline__ void mma_f16(float* c, const uint32_t* a,
                                        uint32_t b0, uint32_t b1) {
    asm volatile(
        "mma.sync.aligned.m16n8k16.row.col.f32.f16.f16.f32 "
        "{%0,%1,%2,%3}, {%4,%5,%6,%7}, {%8,%9}, {%0,%1,%2,%3};\n"
        : "+f"(c[0]), "+f"(c[1]), "+f"(c[2]), "+f"(c[3])
        : "r"(a[0]), "r"(a[1]), "r"(a[2]), "r"(a[3]), "r"(b0), "r"(b1));
}
#define CP_ASYNC16(dst, src) \
    asm volatile("cp.async.cg.shared.global [%0], [%1], 16;\n" :: "r"(dst), "l"(src))
#define CP_COMMIT() asm volatile("cp.async.commit_group;\n" ::: "memory")
template <int N>
__device__ __forceinline__ void cp_wait() {
    asm volatile("cp.async.wait_group %0;\n" :: "n"(N) : "memory");
}

// ---------------------------------------------------------------------------
// Split-conversion kernels (fp16 2-term)
// ---------------------------------------------------------------------------
__global__ void conv_split_A(const float* __restrict__ in,
                             __half* __restrict__ out, int M, int K) {
    int idx = blockIdx.x * blockDim.x + threadIdx.x;
    if (idx >= M * K) return;
    int m = idx / K, k = idx - m * K;
    float a = in[idx];
    __half hi = __float2half(a);
    __half lo = __float2half(a - __half2float(hi));
    size_t base = (size_t)m * (2 * K);
    out[base + k]     = hi;
    out[base + K + k] = lo;
}
__global__ void conv_dup_B(const float* __restrict__ in,
                           __half* __restrict__ out, int K, int N) {
    int idx = blockIdx.x * blockDim.x + threadIdx.x;
    if (idx >= K * N) return;
    int k = idx / N, n = idx - k * N;
    __half hi = __float2half(in[idx]);
    out[(size_t)k * N + n]       = hi;
    out[(size_t)(K + k) * N + n] = hi;
}

// ---------------------------------------------------------------------------
// fp16 TC GEMM: 128x256 CTA tile, BK=32, 4-stage cp.async (wait_group 2),
// 8 warps (2m x 4n), warp tile 64x64.
// ---------------------------------------------------------------------------
#define LDA 40    // halfs per A smem row (32 + 8)
#define LDB 264   // halfs per B smem row (256 + 8)
#define GSTAGES 4
#define G_ASZ (128 * LDA * 2)
#define G_BSZ (32 * LDB * 2)
#define G_STG (G_ASZ + G_BSZ)
#define GEMM_SMEM (GSTAGES * G_STG)

__global__ __launch_bounds__(256, 1) void hgemm256(const __half* __restrict__ A,
                                                   const __half* __restrict__ B,
                                                   float* __restrict__ C,
                                                   int M, int N, int K2) {
    extern __shared__ __half gsm[];

    const int tid  = threadIdx.x;
    const int lane = tid & 31;
    const int w    = tid >> 5;
    const int wm   = (w & 1) * 64;
    const int wn   = (w >> 1) * 64;
    const int rowBase = blockIdx.y * 128;
    const int colBase = blockIdx.x * 256;

    const uint32_t S0 = (uint32_t)__cvta_generic_to_shared(gsm);

    float acc[4][8][4];
#pragma unroll
    for (int mi = 0; mi < 4; mi++)
#pragma unroll
        for (int ni = 0; ni < 8; ni++)
#pragma unroll
            for (int r = 0; r < 4; r++) acc[mi][ni][r] = 0.0f;

    const int NI = K2 / 32;

    auto load_stage = [&](int it, int s) {
        int k0 = it * 32;
        const uint32_t aB = S0 + s * G_STG;
        const uint32_t bB = aB + G_ASZ;
#pragma unroll
        for (int c = 0; c < 2; c++) {               // A: 512 chunks of 16B
            int i = tid + c * 256;
            int row = i >> 2, cc = (i & 3) * 8;
            const __half* src = A + (size_t)(rowBase + row) * K2 + k0 + cc;
            CP_ASYNC16(aB + (row * LDA + cc) * 2, src);
        }
#pragma unroll
        for (int c = 0; c < 4; c++) {               // B: 1024 chunks of 16B
            int i = tid + c * 256;
            int row = i >> 5, cc = (i & 31) * 8;
            const __half* src = B + (size_t)(k0 + row) * N + colBase + cc;
            CP_ASYNC16(bB + (row * LDB + cc) * 2, src);
        }
        CP_COMMIT();
    };

    load_stage(0, 0);
    load_stage(1, 1);
    load_stage(2, 2);

    for (int it = 0; it < NI; ++it) {
        cp_wait<2>();
        __syncthreads();
        if (it + 3 < NI) load_stage(it + 3, (it + 3) & 3);
        else CP_COMMIT();

        const int s = it & 3;
        const uint32_t aB = S0 + s * G_STG;
        const uint32_t bB = aB + G_ASZ;

#pragma unroll
        for (int ks = 0; ks < 32; ks += 16) {
            uint32_t ra[4][4], rb[4][4];
#pragma unroll
            for (int mi = 0; mi < 4; mi++) {
                uint32_t addr = aB +
                    ((wm + mi * 16 + (lane & 15)) * LDA + ks + (lane >> 4) * 8) * 2;
                ldsm_x4(ra[mi][0], ra[mi][1], ra[mi][2], ra[mi][3], addr);
            }
#pragma unroll
            for (int g = 0; g < 4; g++) {
                uint32_t addr = bB +
                    ((ks + (lane & 15)) * LDB + wn + g * 16 + (lane >> 4) * 8) * 2;
                ldsm_x4_t(rb[g][0], rb[g][1], rb[g][2], rb[g][3], addr);
            }
#pragma unroll
            for (int mi = 0; mi < 4; mi++)
#pragma unroll
                for (int ni = 0; ni < 8; ni++)
                    mma_f16(acc[mi][ni], ra[mi],
                            rb[ni >> 1][(ni & 1) * 2], rb[ni >> 1][(ni & 1) * 2 + 1]);
        }
    }

#pragma unroll
    for (int mi = 0; mi < 4; mi++)
#pragma unroll
        for (int ni = 0; ni < 8; ni++) {
            int r = rowBase + wm + mi * 16 + (lane >> 2);
            int cc = colBase + wn + ni * 8 + (lane & 3) * 2;
            *(float2*)&C[(size_t)r * N + cc] =
                make_float2(acc[mi][ni][0], acc[mi][ni][1]);
            *(float2*)&C[(size_t)(r + 8) * N + cc] =
                make_float2(acc[mi][ni][2], acc[mi][ni][3]);
        }
}

// ---------------------------------------------------------------------------
// Fused prep: RoPE + scale + compensated bf16 split + head-major relayout.
// ---------------------------------------------------------------------------
__global__ void prep_kernel(const float* __restrict__ q,
                            const float* __restrict__ kvb,
                            const float* __restrict__ cosb,
                            const float* __restrict__ sinb,
                            __nv_bfloat16* __restrict__ qs,
                            __nv_bfloat16* __restrict__ ks,
                            __nv_bfloat16* __restrict__ vs) {
    const int NQ = Bb * Tt * Hh * 64;
    const int NK = Bb * Tt * KVH * 64;
    const int NV = Bb * Tt * KVH * 128;
    const float scale = 0.08838834764831845f;
    int idx = blockIdx.x * blockDim.x + threadIdx.x;
    if (idx < NQ) {
        int d = idx & 63;
        int h = (idx >> 6) & 15;
        int t = (idx >> 10) & 1023;
        int b = idx >> 20;
        float c = cosb[t * 64 + d];
        float s = sinb[t * 64 + d];
        size_t src = ((size_t)(b * Tt + t) * Hh + h) * HD;
        float u1 = q[src + d], u2 = q[src + 64 + d];
        float r1 = (u1 * c - u2 * s) * scale;
        float r2 = (u1 * s + u2 * c) * scale;
        __nv_bfloat16 h1 = __float2bfloat16(r1);
        __nv_bfloat16 h2 = __float2bfloat16(r2);
        size_t dst = ((size_t)(b * Hh + h) * Tt + t) * 256;
        qs[dst + d]        = h1;
        qs[dst + 128 + d]  = __float2bfloat16(r1 - __bfloat162float(h1));
        qs[dst + 64 + d]   = h2;
        qs[dst + 192 + d]  = __float2bfloat16(r2 - __bfloat162float(h2));
    } else if (idx < NQ + NK) {
        int j = idx - NQ;
        int d = j & 63;
        int kvh = (j >> 6) & 3;
        int t = (j >> 8) & 1023;
        int b = j >> 18;
        float c = cosb[t * 64 + d];
        float s = sinb[t * 64 + d];
        size_t src = ((size_t)(b * Tt + t) * 2) * (KVH * HD) + kvh * HD;
        float u1 = kvb[src + d], u2 = kvb[src + 64 + d];
        float r1 = u1 * c - u2 * s;
        float r2 = u1 * s + u2 * c;
        __nv_bfloat16 h1 = __float2bfloat16(r1);
        __nv_bfloat16 h2 = __float2bfloat16(r2);
        size_t dst = ((size_t)(b * KVH + kvh) * Tt + t) * 256;
        ks[dst + d]        = h1;
        ks[dst + 128 + d]  = __float2bfloat16(r1 - __bfloat162float(h1));
        ks[dst + 64 + d]   = h2;
        ks[dst + 192 + d]  = __float2bfloat16(r2 - __bfloat162float(h2));
    } else if (idx < NQ + NK + NV) {
        int j = idx - NQ - NK;
        int d = j & 127;
        int kvh = (j >> 7) & 3;
        int t = (j >> 9) & 1023;
        int b = j >> 19;
        size_t src = ((size_t)(b * Tt + t) * 2 + 1) * (KVH * HD) + kvh * HD;
        float u = kvb[src + d];
        __nv_bfloat16 hh = __float2bfloat16(u);
        size_t dst = ((size_t)(b * KVH + kvh) * Tt + t) * 256;
        vs[dst + d]       = hh;
        vs[dst + 128 + d] = __float2bfloat16(u - __bfloat162float(hh));
    }
}

// ---------------------------------------------------------------------------
// Tensor-core flash attention (bf16 3-term), cp.async double-buffered K/V.
// CTA: 64 q rows of one (b,h). 128 threads = 4 warps.
// ---------------------------------------------------------------------------
#define LDH 264
#define F_QSZ (64 * LDH * 2)
#define F_STG (64 * LDH * 2)
#define FLASH_SMEM (F_QSZ + 4 * F_STG)   // Q + 2xK + 2xV

__global__ __launch_bounds__(128, 1) void flash_tc(const __nv_bfloat16* __restrict__ qs,
                                                   const __nv_bfloat16* __restrict__ ks,
                                                   const __nv_bfloat16* __restrict__ vs,
                                                   float* __restrict__ ctx) {
    extern __shared__ __nv_bfloat16 fsm[];

    const int qtile = blockIdx.x;
    const int h     = blockIdx.y;
    const int b     = blockIdx.z;
    const int kvh   = h >> 2;
    const int qbase = qtile * 64;

    const int tid  = threadIdx.x;
    const int lane = tid & 31;
    const int w    = tid >> 5;
    const int gid  = lane >> 2;
    const int tig  = lane & 3;

    const uint32_t QsA = (uint32_t)__cvta_generic_to_shared(fsm);
    const uint32_t KsA = QsA + F_QSZ;
    const uint32_t VsA = KsA + 2 * F_STG;

    // Q load: 64 rows x 32 chunks of 16B = 2048 chunks, 16 per thread
    {
        const __nv_bfloat16* qsrc = qs + ((size_t)(b * Hh + h) * Tt + qbase) * 256;
#pragma unroll
        for (int i = 0; i < 16; i++) {
            int c = tid + i * 128;
            int r = c >> 5, cc = (c & 31) * 8;
            CP_ASYNC16(QsA + (r * LDH + cc) * 2, qsrc + r * 256 + cc);
        }
        CP_COMMIT();
    }

    auto load_kv = [&](int kt, int s) {
        const __nv_bfloat16* kb = ks + ((size_t)(b * KVH + kvh) * Tt + kt * 64) * 256;
        const __nv_bfloat16* vb = vs + ((size_t)(b * KVH + kvh) * Tt + kt * 64) * 256;
        const uint32_t kd = KsA + s * F_STG;
        const uint32_t vd = VsA + s * F_STG;
#pragma unroll
        for (int i = 0; i < 16; i++) {
            int c = tid + i * 128;
            int r = c >> 5, cc = (c & 31) * 8;
            CP_ASYNC16(kd + (r * LDH + cc) * 2, kb + r * 256 + cc);
        }
#pragma unroll
        for (int i = 0; i < 16; i++) {
            int c = tid + i * 128;
            int r = c >> 5, cc = (c & 31) * 8;
            CP_ASYNC16(vd + (r * LDH + cc) * 2, vb + r * 256 + cc);
        }
        CP_COMMIT();
    };

    load_kv(0, 0);

    float oacc[16][4];
#pragma unroll
    for (int t = 0; t < 16; t++)
#pragma unroll
        for (int r = 0; r < 4; r++) oacc[t][r] = 0.0f;
    float m0 = -INFINITY, m1 = -INFINITY, l0 = 0.0f, l1 = 0.0f;

    for (int kt = 0; kt <= qtile; ++kt) {
        if (kt < qtile) load_kv(kt + 1, (kt + 1) & 1);
        else CP_COMMIT();
        cp_wait<1>();
        __syncthreads();

        const uint32_t kB = KsA + (kt & 1) * F_STG;
        const uint32_t vB = VsA + (kt & 1) * F_STG;

        // S = Qh Kh^T + Qh Kl^T + Ql Kh^T
        float sacc[8][4];
#pragma unroll
        for (int t = 0; t < 8; t++)
#pragma unroll
            for (int r = 0; r < 4; r++) sacc[t][r] = 0.0f;

#pragma unroll
        for (int kc = 0; kc < 8; kc++) {
            uint32_t qh[4], ql[4];
            uint32_t aaddr = QsA +
                ((w * 16 + (lane & 15)) * LDH + kc * 16 + (lane >> 4) * 8) * 2;
            ldsm_x4(qh[0], qh[1], qh[2], qh[3], aaddr);
            ldsm_x4(ql[0], ql[1], ql[2], ql[3], aaddr + 256);
#pragma unroll
            for (int g = 0; g < 4; g++) {
                uint32_t kh[4], kl[4];
                uint32_t baddr = kB +
                    ((g * 16 + (lane & 15)) * LDH + kc * 16 + (lane >> 4) * 8) * 2;
                ldsm_x4(kh[0], kh[1], kh[2], kh[3], baddr);
                ldsm_x4(kl[0], kl[1], kl[2], kl[3], baddr + 256);
                mma_bf16(sacc[2 * g],     qh, kh[0], kh[2]);
                mma_bf16(sacc[2 * g + 1], qh, kh[1], kh[3]);
                mma_bf16(sacc[2 * g],     qh, kl[0], kl[2]);
                mma_bf16(sacc[2 * g + 1], qh, kl[1], kl[3]);
                mma_bf16(sacc[2 * g],     ql, kh[0], kh[2]);
                mma_bf16(sacc[2 * g + 1], ql, kh[1], kh[3]);
            }
        }

        if (kt == qtile) {
            int row0 = w * 16 + gid;
#pragma unroll
            for (int s8 = 0; s8 < 8; s8++) {
                int cb = s8 * 8 + tig * 2;
                if (cb     > row0)     sacc[s8][0] = -INFINITY;
                if (cb + 1 > row0)     sacc[s8][1] = -INFINITY;
                if (cb     > row0 + 8) sacc[s8][2] = -INFINITY;
                if (cb + 1 > row0 + 8) sacc[s8][3] = -INFINITY;
            }
        }

        float mx0 = -INFINITY, mx1 = -INFINITY;
#pragma unroll
        for (int s8 = 0; s8 < 8; s8++) {
            mx0 = fmaxf(mx0, fmaxf(sacc[s8][0], sacc[s8][1]));
            mx1 = fmaxf(mx1, fmaxf(sacc[s8][2], sacc[s8][3]));
        }
#pragma unroll
        for (int o = 1; o < 4; o <<= 1) {
            mx0 = fmaxf(mx0, __shfl_xor_sync(0xffffffffu, mx0, o));
            mx1 = fmaxf(mx1, __shfl_xor_sync(0xffffffffu, mx1, o));
        }
        float mn0 = fmaxf(m0, mx0), mn1 = fmaxf(m1, mx1);
        float f0 = __expf(m0 - mn0), f1 = __expf(m1 - mn1);
        float rs0 = 0.0f, rs1 = 0.0f;
#pragma unroll
        for (int s8 = 0; s8 < 8; s8++) {
            sacc[s8][0] = __expf(sacc[s8][0] - mn0);
            sacc[s8][1] = __expf(sacc[s8][1] - mn0);
            sacc[s8][2] = __expf(sacc[s8][2] - mn1);
            sacc[s8][3] = __expf(sacc[s8][3] - mn1);
            rs0 += sacc[s8][0] + sacc[s8][1];
            rs1 += sacc[s8][2] + sacc[s8][3];
        }
#pragma unroll
        for (int o = 1; o < 4; o <<= 1) {
            rs0 += __shfl_xor_sync(0xffffffffu, rs0, o);
            rs1 += __shfl_xor_sync(0xffffffffu, rs1, o);
        }
        l0 = l0 * f0 + rs0; m0 = mn0;
        l1 = l1 * f1 + rs1; m1 = mn1;
#pragma unroll
        for (int t = 0; t < 16; t++) {
            oacc[t][0] *= f0; oacc[t][1] *= f0;
            oacc[t][2] *= f1; oacc[t][3] *= f1;
        }

        // Repack P (hi + lo)
        uint32_t aPh[4][4], aPl[4][4];
#pragma unroll
        for (int j = 0; j < 4; j++) {
#pragma unroll
            for (int half = 0; half < 2; half++) {
                int t = 2 * j + half;
                float x0 = sacc[t][0], x1 = sacc[t][1];
                float x2 = sacc[t][2], x3 = sacc[t][3];
                __nv_bfloat16 h0 = __float2bfloat16(x0);
                __nv_bfloat16 h1 = __float2bfloat16(x1);
                __nv_bfloat16 h2 = __float2bfloat16(x2);
                __nv_bfloat16 h3 = __float2bfloat16(x3);
                __nv_bfloat162 ph01(h0, h1), ph23(h2, h3);
                aPh[j][2 * half]     = *(uint32_t*)&ph01;
                aPh[j][2 * half + 1] = *(uint32_t*)&ph23;
                __nv_bfloat162 pl01(__float2bfloat16(x0 - __bfloat162float(h0)),
                                    __float2bfloat16(x1 - __bfloat162float(h1)));
                __nv_bfloat162 pl23(__float2bfloat16(x2 - __bfloat162float(h2)),
                                    __float2bfloat16(x3 - __bfloat162float(h3)));
                aPl[j][2 * half]     = *(uint32_t*)&pl01;
                aPl[j][2 * half + 1] = *(uint32_t*)&pl23;
            }
        }

        // O += Ph Vh + Pl Vh + Ph Vl
#pragma unroll
        for (int j = 0; j < 4; j++) {
#pragma unroll
            for (int g = 0; g < 8; g++) {
                uint32_t vh[4], vl[4];
                uint32_t baddr = vB +
                    ((j * 16 + (lane & 15)) * LDH + g * 16 + (lane >> 4) * 8) * 2;
                ldsm_x4_t(vh[0], vh[1], vh[2], vh[3], baddr);
                ldsm_x4_t(vl[0], vl[1], vl[2], vl[3], baddr + 256);
                mma_bf16(oacc[2 * g],     aPh[j], vh[0], vh[1]);
                mma_bf16(oacc[2 * g + 1], aPh[j], vh[2], vh[3]);
                mma_bf16(oacc[2 * g],     aPl[j], vh[0], vh[1]);
                mma_bf16(oacc[2 * g + 1], aPl[j], vh[2], vh[3]);
                mma_bf16(oacc[2 * g],     aPh[j], vl[0], vl[1]);
                mma_bf16(oacc[2 * g + 1], aPh[j], vl[2], vl[3]);
            }
        }
        __syncthreads();   // protect stage reuse by next iteration's load
    }

    float inv0 = 1.0f / l0, inv1 = 1.0f / l1;
    int r0g = qbase + w * 16 + gid;
#pragma unroll
    for (int t = 0; t < 16; t++) {
        int dcol = t * 8 + tig * 2;
        size_t base0 = (size_t)(b * Tt + r0g) * DIM + h * HD + dcol;
        size_t base1 = (size_t)(b * Tt + r0g + 8) * DIM + h * HD + dcol;
        *(float2*)&ctx[base0] = make_float2(oacc[t][0] * inv0, oacc[t][1] * inv0);
        *(float2*)&ctx[base1] = make_float2(oacc[t][2] * inv1, oacc[t][3] * inv1);
    }
}

// ---------------------------------------------------------------------------
// Launch
// ---------------------------------------------------------------------------
extern "C" void kernel_launch(void* const* d_in, const int* in_sizes, int n_in,
                              void* d_out, int out_size) {
    const float* x    = (const float*)d_in[0];
    const float* Wq   = (const float*)d_in[1];
    const float* Wkv  = (const float*)d_in[2];
    const float* Wo   = (const float*)d_in[3];
    const float* cosb = (const float*)d_in[4];
    const float* sinb = (const float*)d_in[5];
    float* out = (float*)d_out;

    float *qbuf, *kvbuf, *ctxbuf;
    __half *xs, *ctxs, *wqs, *wkvs, *wos;
    __nv_bfloat16 *qsb, *ksb, *vsb;
    cudaGetSymbolAddress((void**)&qbuf,   g_q);
    cudaGetSymbolAddress((void**)&kvbuf,  g_kv);
    cudaGetSymbolAddress((void**)&ctxbuf, g_ctx);
    cudaGetSymbolAddress((void**)&xs,     g_xs);
    cudaGetSymbolAddress((void**)&ctxs,   g_ctxs);
    cudaGetSymbolAddress((void**)&wqs,    g_wqs);
    cudaGetSymbolAddress((void**)&wkvs,   g_wkvs);
    cudaGetSymbolAddress((void**)&wos,    g_wos);
    cudaGetSymbolAddress((void**)&qsb,    g_qs);
    cudaGetSymbolAddress((void**)&ksb,    g_ks);
    cudaGetSymbolAddress((void**)&vsb,    g_vs);

    cudaFuncSetAttribute(hgemm256, cudaFuncAttributeMaxDynamicSharedMemorySize,
                         GEMM_SMEM);
    cudaFuncSetAttribute(flash_tc, cudaFuncAttributeMaxDynamicSharedMemorySize,
                         FLASH_SMEM);

    const int M = MROWS;  // 4096

    // Split conversions (fp16 2-term)
    conv_split_A<<<(M * DIM + 255) / 256, 256>>>(x, xs, M, DIM);
    conv_dup_B<<<(DIM * DIM + 255) / 256, 256>>>(Wq, wqs, DIM, DIM);
    conv_dup_B<<<(DIM * NKV + 255) / 256, 256>>>(Wkv, wkvs, DIM, NKV);
    conv_dup_B<<<(DIM * DIM + 255) / 256, 256>>>(Wo, wos, DIM, DIM);

    // q = x @ Wq ; kv = x @ Wkv
    hgemm256<<<dim3(DIM / 256, M / 128), 256, GEMM_SMEM>>>(xs, wqs, qbuf, M, DIM, K2Q);
    hgemm256<<<dim3(NKV / 256, M / 128), 256, GEMM_SMEM>>>(xs, wkvs, kvbuf, M, NKV, K2Q);

    // fused rope + split + relayout
    {
        int total = Bb * Tt * Hh * 64 + Bb * Tt * KVH * 64 + Bb * Tt * KVH * 128;
        prep_kernel<<<(total + 255) / 256, 256>>>(qbuf, kvbuf, cosb, sinb,
                                                  qsb, ksb, vsb);
    }

    // attention (bf16 3-term, proven accurate)
    flash_tc<<<dim3(Tt / 64, Hh, Bb), 128, FLASH_SMEM>>>(qsb, ksb, vsb, ctxbuf);

    // out = ctx @ Wo
    conv_split_A<<<(M * DIM + 255) / 256, 256>>>(ctxbuf, ctxs, M, DIM);
    hgemm256<<<dim3(DIM / 256, M / 128), 256, GEMM_SMEM>>>(ctxs, wos, out, M, DIM, K2Q);
}

// round 9
// speedup vs baseline: 3.8679x; 1.1093x over previous
#include <cuda_runtime.h>
#include <cuda_bf16.h>
#include <cuda_fp16.h>
#include <math.h>
#include <stdint.h>

// Problem constants
#define Bb   4
#define Tt   1024
#define DIM  2048
#define Hh   16
#define KVH  4
#define Gg   4
#define HD   128

#define MROWS (Bb * Tt)          // 4096
#define K2Q   (2 * DIM)          // 4096 (fp16 2-term split-K layout for A)
#define NKV   (2 * KVH * HD)     // 1024

// fp32 scratch
__device__ __align__(256) float g_q  [MROWS * DIM];
__device__ __align__(256) float g_kv [MROWS * NKV];

// fp16 scratch:
// A-layouts: [M, 2K] = [Ah | Al].  B-layouts: plain [K, N] fp16 (single copy).
__device__ __align__(256) __half g_xs  [MROWS * K2Q];
__device__ __align__(256) __half g_ctxs[MROWS * K2Q];
__device__ __align__(256) __half g_wqs [DIM * DIM];
__device__ __align__(256) __half g_wkvs[DIM * NKV];
__device__ __align__(256) __half g_wos [DIM * DIM];

// pre-split attention operands (rope + scale applied), bf16 3-term path:
__device__ __align__(256) __nv_bfloat16 g_qs[Bb * Hh * Tt * 256];
__device__ __align__(256) __nv_bfloat16 g_ks[Bb * KVH * Tt * 256];
__device__ __align__(256) __nv_bfloat16 g_vs[Bb * KVH * Tt * 256];

// ---------------------------------------------------------------------------
// PTX helpers
// ---------------------------------------------------------------------------
__device__ __forceinline__ void ldsm_x4(uint32_t& r0, uint32_t& r1,
                                        uint32_t& r2, uint32_t& r3, uint32_t addr) {
    asm volatile("ldmatrix.sync.aligned.m8n8.x4.shared.b16 {%0,%1,%2,%3}, [%4];\n"
                 : "=r"(r0), "=r"(r1), "=r"(r2), "=r"(r3) : "r"(addr));
}
__device__ __forceinline__ void ldsm_x4_t(uint32_t& r0, uint32_t& r1,
                                          uint32_t& r2, uint32_t& r3, uint32_t addr) {
    asm volatile("ldmatrix.sync.aligned.m8n8.x4.trans.shared.b16 {%0,%1,%2,%3}, [%4];\n"
                 : "=r"(r0), "=r"(r1), "=r"(r2), "=r"(r3) : "r"(addr));
}
__device__ __forceinline__ void mma_bf16(float* c, const uint32_t* a,
                                         uint32_t b0, uint32_t b1) {
    asm volatile(
        "mma.sync.aligned.m16n8k16.row.col.f32.bf16.bf16.f32 "
        "{%0,%1,%2,%3}, {%4,%5,%6,%7}, {%8,%9}, {%0,%1,%2,%3};\n"
        : "+f"(c[0]), "+f"(c[1]), "+f"(c[2]), "+f"(c[3])
        : "r"(a[0]), "r"(a[1]), "r"(a[2]), "r"(a[3]), "r"(b0), "r"(b1));
}
__device__ __forceinline__ void mma_f16(float* c, const uint32_t* a,
                                        uint32_t b0, uint32_t b1) {
    asm volatile(
        "mma.sync.aligned.m16n8k16.row.col.f32.f16.f16.f32 "
        "{%0,%1,%2,%3}, {%4,%5,%6,%7}, {%8,%9}, {%0,%1,%2,%3};\n"
        : "+f"(c[0]), "+f"(c[1]), "+f"(c[2]), "+f"(c[3])
        : "r"(a[0]), "r"(a[1]), "r"(a[2]), "r"(a[3]), "r"(b0), "r"(b1));
}
// fp16-accumulator HMMA (possibly double-rate)
__device__ __forceinline__ void mma_f16acc(uint32_t* c, const uint32_t* a,
                                           uint32_t b0, uint32_t b1) {
    asm volatile(
        "mma.sync.aligned.m16n8k16.row.col.f16.f16.f16.f16 "
        "{%0,%1}, {%2,%3,%4,%5}, {%6,%7}, {%0,%1};\n"
        : "+r"(c[0]), "+r"(c[1])
        : "r"(a[0]), "r"(a[1]), "r"(a[2]), "r"(a[3]), "r"(b0), "r"(b1));
}
#define CP_ASYNC16(dst, src) \
    asm volatile("cp.async.cg.shared.global [%0], [%1], 16;\n" :: "r"(dst), "l"(src))
#define CP_COMMIT() asm volatile("cp.async.commit_group;\n" ::: "memory")
template <int N>
__device__ __forceinline__ void cp_wait() {
    asm volatile("cp.async.wait_group %0;\n" :: "n"(N) : "memory");
}

// ---------------------------------------------------------------------------
// Conversion kernels
// ---------------------------------------------------------------------------
__global__ void conv_split_A(const float* __restrict__ in,
                             __half* __restrict__ out, int M, int K) {
    int idx = blockIdx.x * blockDim.x + threadIdx.x;
    if (idx >= M * K) return;
    int m = idx / K, k = idx - m * K;
    float a = in[idx];
    __half hi = __float2half(a);
    __half lo = __float2half(a - __half2float(hi));
    size_t base = (size_t)m * (2 * K);
    out[base + k]     = hi;
    out[base + K + k] = lo;
}
__global__ void conv_h(const float* __restrict__ in,
                       __half* __restrict__ out, int n) {
    int idx = blockIdx.x * blockDim.x + threadIdx.x;
    if (idx < n) out[idx] = __float2half(in[idx]);
}

// ---------------------------------------------------------------------------
// fp16 TC GEMM with asymmetric-precision split:
//   C = Ah@B (f32-acc HMMA) + Al@B (f16-acc HMMA, possibly 2x rate)
// A: [M,2K] = [Ah|Al]; B: [K,N] single fp16.
// 128x256 CTA tile, BK=32, 4-stage cp.async (wait_group 2), 8 warps 64x64.
// ---------------------------------------------------------------------------
#define LDA 40    // halfs per A smem row (32 + 8)
#define LDB 264   // halfs per B smem row (256 + 8)
#define GSTAGES 4
#define A_HALF (128 * LDA * 2)        // bytes per A half (hi or lo)
#define G_ASZ  (2 * A_HALF)
#define G_BSZ  (32 * LDB * 2)
#define G_STG  (G_ASZ + G_BSZ)
#define GEMM_SMEM (GSTAGES * G_STG)

__global__ __launch_bounds__(256, 1) void hgemm256(const __half* __restrict__ A,
                                                   const __half* __restrict__ B,
                                                   float* __restrict__ C,
                                                   int M, int N, int K) {
    extern __shared__ __half gsm[];

    const int tid  = threadIdx.x;
    const int lane = tid & 31;
    const int w    = tid >> 5;
    const int wm   = (w & 1) * 64;
    const int wn   = (w >> 1) * 64;
    const int rowBase = blockIdx.y * 128;
    const int colBase = blockIdx.x * 256;
    const int K2 = 2 * K;

    const uint32_t S0 = (uint32_t)__cvta_generic_to_shared(gsm);

    float acc[4][8][4];
#pragma unroll
    for (int mi = 0; mi < 4; mi++)
#pragma unroll
        for (int ni = 0; ni < 8; ni++)
#pragma unroll
            for (int r = 0; r < 4; r++) acc[mi][ni][r] = 0.0f;
    uint32_t acc2[4][8][2];
#pragma unroll
    for (int mi = 0; mi < 4; mi++)
#pragma unroll
        for (int ni = 0; ni < 8; ni++) { acc2[mi][ni][0] = 0u; acc2[mi][ni][1] = 0u; }

    const int NI = K / 32;

    auto load_stage = [&](int it, int s) {
        int k0 = it * 32;
        const uint32_t aB = S0 + s * G_STG;
        const uint32_t bB = aB + G_ASZ;
#pragma unroll
        for (int c = 0; c < 2; c++) {               // A hi: 512 chunks of 16B
            int i = tid + c * 256;
            int row = i >> 2, cc = (i & 3) * 8;
            const __half* src = A + (size_t)(rowBase + row) * K2 + k0 + cc;
            CP_ASYNC16(aB + (row * LDA + cc) * 2, src);
        }
#pragma unroll
        for (int c = 0; c < 2; c++) {               // A lo: 512 chunks
            int i = tid + c * 256;
            int row = i >> 2, cc = (i & 3) * 8;
            const __half* src = A + (size_t)(rowBase + row) * K2 + K + k0 + cc;
            CP_ASYNC16(aB + A_HALF + (row * LDA + cc) * 2, src);
        }
#pragma unroll
        for (int c = 0; c < 4; c++) {               // B: 1024 chunks
            int i = tid + c * 256;
            int row = i >> 5, cc = (i & 31) * 8;
            const __half* src = B + (size_t)(k0 + row) * N + colBase + cc;
            CP_ASYNC16(bB + (row * LDB + cc) * 2, src);
        }
        CP_COMMIT();
    };

    load_stage(0, 0);
    load_stage(1, 1);
    load_stage(2, 2);

    for (int it = 0; it < NI; ++it) {
        cp_wait<2>();
        __syncthreads();
        if (it + 3 < NI) load_stage(it + 3, (it + 3) & 3);
        else CP_COMMIT();

        const int s = it & 3;
        const uint32_t aB = S0 + s * G_STG;
        const uint32_t bB = aB + G_ASZ;

#pragma unroll
        for (int ks = 0; ks < 32; ks += 16) {
            uint32_t ra[4][4], rb[4][4];
#pragma unroll
            for (int g = 0; g < 4; g++) {
                uint32_t addr = bB +
                    ((ks + (lane & 15)) * LDB + wn + g * 16 + (lane >> 4) * 8) * 2;
                ldsm_x4_t(rb[g][0], rb[g][1], rb[g][2], rb[g][3], addr);
            }
            // hi term: f32-acc
#pragma unroll
            for (int mi = 0; mi < 4; mi++) {
                uint32_t addr = aB +
                    ((wm + mi * 16 + (lane & 15)) * LDA + ks + (lane >> 4) * 8) * 2;
                ldsm_x4(ra[mi][0], ra[mi][1], ra[mi][2], ra[mi][3], addr);
            }
#pragma unroll
            for (int mi = 0; mi < 4; mi++)
#pragma unroll
                for (int ni = 0; ni < 8; ni++)
                    mma_f16(acc[mi][ni], ra[mi],
                            rb[ni >> 1][(ni & 1) * 2], rb[ni >> 1][(ni & 1) * 2 + 1]);
            // lo term: f16-acc (reuse ra registers)
#pragma unroll
            for (int mi = 0; mi < 4; mi++) {
                uint32_t addr = aB + A_HALF +
                    ((wm + mi * 16 + (lane & 15)) * LDA + ks + (lane >> 4) * 8) * 2;
                ldsm_x4(ra[mi][0], ra[mi][1], ra[mi][2], ra[mi][3], addr);
            }
#pragma unroll
            for (int mi = 0; mi < 4; mi++)
#pragma unroll
                for (int ni = 0; ni < 8; ni++)
                    mma_f16acc(acc2[mi][ni], ra[mi],
                               rb[ni >> 1][(ni & 1) * 2], rb[ni >> 1][(ni & 1) * 2 + 1]);
        }
    }

#pragma unroll
    for (int mi = 0; mi < 4; mi++)
#pragma unroll
        for (int ni = 0; ni < 8; ni++) {
            int r = rowBase + wm + mi * 16 + (lane >> 2);
            int cc = colBase + wn + ni * 8 + (lane & 3) * 2;
            float2 lo0 = __half22float2(*(__half2*)&acc2[mi][ni][0]);
            float2 lo1 = __half22float2(*(__half2*)&acc2[mi][ni][1]);
            *(float2*)&C[(size_t)r * N + cc] =
                make_float2(acc[mi][ni][0] + lo0.x, acc[mi][ni][1] + lo0.y);
            *(float2*)&C[(size_t)(r + 8) * N + cc] =
                make_float2(acc[mi][ni][2] + lo1.x, acc[mi][ni][3] + lo1.y);
        }
}

// ---------------------------------------------------------------------------
// Fused prep: RoPE + scale + compensated bf16 split + head-major relayout.
// ---------------------------------------------------------------------------
__global__ void prep_kernel(const float* __restrict__ q,
                            const float* __restrict__ kvb,
                            const float* __restrict__ cosb,
                            const float* __restrict__ sinb,
                            __nv_bfloat16* __restrict__ qs,
                            __nv_bfloat16* __restrict__ ks,
                            __nv_bfloat16* __restrict__ vs) {
    const int NQ = Bb * Tt * Hh * 64;
    const int NK = Bb * Tt * KVH * 64;
    const int NV = Bb * Tt * KVH * 128;
    const float scale = 0.08838834764831845f;
    int idx = blockIdx.x * blockDim.x + threadIdx.x;
    if (idx < NQ) {
        int d = idx & 63;
        int h = (idx >> 6) & 15;
        int t = (idx >> 10) & 1023;
        int b = idx >> 20;
        float c = cosb[t * 64 + d];
        float s = sinb[t * 64 + d];
        size_t src = ((size_t)(b * Tt + t) * Hh + h) * HD;
        float u1 = q[src + d], u2 = q[src + 64 + d];
        float r1 = (u1 * c - u2 * s) * scale;
        float r2 = (u1 * s + u2 * c) * scale;
        __nv_bfloat16 h1 = __float2bfloat16(r1);
        __nv_bfloat16 h2 = __float2bfloat16(r2);
        size_t dst = ((size_t)(b * Hh + h) * Tt + t) * 256;
        qs[dst + d]        = h1;
        qs[dst + 128 + d]  = __float2bfloat16(r1 - __bfloat162float(h1));
        qs[dst + 64 + d]   = h2;
        qs[dst + 192 + d]  = __float2bfloat16(r2 - __bfloat162float(h2));
    } else if (idx < NQ + NK) {
        int j = idx - NQ;
        int d = j & 63;
        int kvh = (j >> 6) & 3;
        int t = (j >> 8) & 1023;
        int b = j >> 18;
        float c = cosb[t * 64 + d];
        float s = sinb[t * 64 + d];
        size_t src = ((size_t)(b * Tt + t) * 2) * (KVH * HD) + kvh * HD;
        float u1 = kvb[src + d], u2 = kvb[src + 64 + d];
        float r1 = u1 * c - u2 * s;
        float r2 = u1 * s + u2 * c;
        __nv_bfloat16 h1 = __float2bfloat16(r1);
        __nv_bfloat16 h2 = __float2bfloat16(r2);
        size_t dst = ((size_t)(b * KVH + kvh) * Tt + t) * 256;
        ks[dst + d]        = h1;
        ks[dst + 128 + d]  = __float2bfloat16(r1 - __bfloat162float(h1));
        ks[dst + 64 + d]   = h2;
        ks[dst + 192 + d]  = __float2bfloat16(r2 - __bfloat162float(h2));
    } else if (idx < NQ + NK + NV) {
        int j = idx - NQ - NK;
        int d = j & 127;
        int kvh = (j >> 7) & 3;
        int t = (j >> 9) & 1023;
        int b = j >> 19;
        size_t src = ((size_t)(b * Tt + t) * 2 + 1) * (KVH * HD) + kvh * HD;
        float u = kvb[src + d];
        __nv_bfloat16 hh = __float2bfloat16(u);
        size_t dst = ((size_t)(b * KVH + kvh) * Tt + t) * 256;
        vs[dst + d]       = hh;
        vs[dst + 128 + d] = __float2bfloat16(u - __bfloat162float(hh));
    }
}

// ---------------------------------------------------------------------------
// Tensor-core flash attention (bf16 3-term), cp.async double-buffered K/V.
// Epilogue writes the fp16 [Ch|Cl] split layout directly into g_ctxs.
// ---------------------------------------------------------------------------
#define LDH 264
#define F_QSZ (64 * LDH * 2)
#define F_STG (64 * LDH * 2)
#define FLASH_SMEM (F_QSZ + 4 * F_STG)   // Q + 2xK + 2xV

__global__ __launch_bounds__(128, 1) void flash_tc(const __nv_bfloat16* __restrict__ qs,
                                                   const __nv_bfloat16* __restrict__ ks,
                                                   const __nv_bfloat16* __restrict__ vs,
                                                   __half* __restrict__ ctxs) {
    extern __shared__ __nv_bfloat16 fsm[];

    const int qtile = blockIdx.x;
    const int h     = blockIdx.y;
    const int b     = blockIdx.z;
    const int kvh   = h >> 2;
    const int qbase = qtile * 64;

    const int tid  = threadIdx.x;
    const int lane = tid & 31;
    const int w    = tid >> 5;
    const int gid  = lane >> 2;
    const int tig  = lane & 3;

    const uint32_t QsA = (uint32_t)__cvta_generic_to_shared(fsm);
    const uint32_t KsA = QsA + F_QSZ;
    const uint32_t VsA = KsA + 2 * F_STG;

    {
        const __nv_bfloat16* qsrc = qs + ((size_t)(b * Hh + h) * Tt + qbase) * 256;
#pragma unroll
        for (int i = 0; i < 16; i++) {
            int c = tid + i * 128;
            int r = c >> 5, cc = (c & 31) * 8;
            CP_ASYNC16(QsA + (r * LDH + cc) * 2, qsrc + r * 256 + cc);
        }
        CP_COMMIT();
    }

    auto load_kv = [&](int kt, int s) {
        const __nv_bfloat16* kb = ks + ((size_t)(b * KVH + kvh) * Tt + kt * 64) * 256;
        const __nv_bfloat16* vb = vs + ((size_t)(b * KVH + kvh) * Tt + kt * 64) * 256;
        const uint32_t kd = KsA + s * F_STG;
        const uint32_t vd = VsA + s * F_STG;
#pragma unroll
        for (int i = 0; i < 16; i++) {
            int c = tid + i * 128;
            int r = c >> 5, cc = (c & 31) * 8;
            CP_ASYNC16(kd + (r * LDH + cc) * 2, kb + r * 256 + cc);
        }
#pragma unroll
        for (int i = 0; i < 16; i++) {
            int c = tid + i * 128;
            int r = c >> 5, cc = (c & 31) * 8;
            CP_ASYNC16(vd + (r * LDH + cc) * 2, vb + r * 256 + cc);
        }
        CP_COMMIT();
    };

    load_kv(0, 0);

    float oacc[16][4];
#pragma unroll
    for (int t = 0; t < 16; t++)
#pragma unroll
        for (int r = 0; r < 4; r++) oacc[t][r] = 0.0f;
    float m0 = -INFINITY, m1 = -INFINITY, l0 = 0.0f, l1 = 0.0f;

    for (int kt = 0; kt <= qtile; ++kt) {
        if (kt < qtile) load_kv(kt + 1, (kt + 1) & 1);
        else CP_COMMIT();
        cp_wait<1>();
        __syncthreads();

        const uint32_t kB = KsA + (kt & 1) * F_STG;
        const uint32_t vB = VsA + (kt & 1) * F_STG;

        float sacc[8][4];
#pragma unroll
        for (int t = 0; t < 8; t++)
#pragma unroll
            for (int r = 0; r < 4; r++) sacc[t][r] = 0.0f;

#pragma unroll
        for (int kc = 0; kc < 8; kc++) {
            uint32_t qh[4], ql[4];
            uint32_t aaddr = QsA +
                ((w * 16 + (lane & 15)) * LDH + kc * 16 + (lane >> 4) * 8) * 2;
            ldsm_x4(qh[0], qh[1], qh[2], qh[3], aaddr);
            ldsm_x4(ql[0], ql[1], ql[2], ql[3], aaddr + 256);
#pragma unroll
            for (int g = 0; g < 4; g++) {
                uint32_t kh[4], kl[4];
                uint32_t baddr = kB +
                    ((g * 16 + (lane & 15)) * LDH + kc * 16 + (lane >> 4) * 8) * 2;
                ldsm_x4(kh[0], kh[1], kh[2], kh[3], baddr);
                ldsm_x4(kl[0], kl[1], kl[2], kl[3], baddr + 256);
                mma_bf16(sacc[2 * g],     qh, kh[0], kh[2]);
                mma_bf16(sacc[2 * g + 1], qh, kh[1], kh[3]);
                mma_bf16(sacc[2 * g],     qh, kl[0], kl[2]);
                mma_bf16(sacc[2 * g + 1], qh, kl[1], kl[3]);
                mma_bf16(sacc[2 * g],     ql, kh[0], kh[2]);
                mma_bf16(sacc[2 * g + 1], ql, kh[1], kh[3]);
            }
        }

        if (kt == qtile) {
            int row0 = w * 16 + gid;
#pragma unroll
            for (int s8 = 0; s8 < 8; s8++) {
                int cb = s8 * 8 + tig * 2;
                if (cb     > row0)     sacc[s8][0] = -INFINITY;
                if (cb + 1 > row0)     sacc[s8][1] = -INFINITY;
                if (cb     > row0 + 8) sacc[s8][2] = -INFINITY;
                if (cb + 1 > row0 + 8) sacc[s8][3] = -INFINITY;
            }
        }

        float mx0 = -INFINITY, mx1 = -INFINITY;
#pragma unroll
        for (int s8 = 0; s8 < 8; s8++) {
            mx0 = fmaxf(mx0, fmaxf(sacc[s8][0], sacc[s8][1]));
            mx1 = fmaxf(mx1, fmaxf(sacc[s8][2], sacc[s8][3]));
        }
#pragma unroll
        for (int o = 1; o < 4; o <<= 1) {
            mx0 = fmaxf(mx0, __shfl_xor_sync(0xffffffffu, mx0, o));
            mx1 = fmaxf(mx1, __shfl_xor_sync(0xffffffffu, mx1, o));
        }
        float mn0 = fmaxf(m0, mx0), mn1 = fmaxf(m1, mx1);
        float f0 = __expf(m0 - mn0), f1 = __expf(m1 - mn1);
        float rs0 = 0.0f, rs1 = 0.0f;
#pragma unroll
        for (int s8 = 0; s8 < 8; s8++) {
            sacc[s8][0] = __expf(sacc[s8][0] - mn0);
            sacc[s8][1] = __expf(sacc[s8][1] - mn0);
            sacc[s8][2] = __expf(sacc[s8][2] - mn1);
            sacc[s8][3] = __expf(sacc[s8][3] - mn1);
            rs0 += sacc[s8][0] + sacc[s8][1];
            rs1 += sacc[s8][2] + sacc[s8][3];
        }
#pragma unroll
        for (int o = 1; o < 4; o <<= 1) {
            rs0 += __shfl_xor_sync(0xffffffffu, rs0, o);
            rs1 += __shfl_xor_sync(0xffffffffu, rs1, o);
        }
        l0 = l0 * f0 + rs0; m0 = mn0;
        l1 = l1 * f1 + rs1; m1 = mn1;
#pragma unroll
        for (int t = 0; t < 16; t++) {
            oacc[t][0] *= f0; oacc[t][1] *= f0;
            oacc[t][2] *= f1; oacc[t][3] *= f1;
        }

        uint32_t aPh[4][4], aPl[4][4];
#pragma unroll
        for (int j = 0; j < 4; j++) {
#pragma unroll
            for (int half = 0; half < 2; half++) {
                int t = 2 * j + half;
                float x0 = sacc[t][0], x1 = sacc[t][1];
                float x2 = sacc[t][2], x3 = sacc[t][3];
                __nv_bfloat16 h0 = __float2bfloat16(x0);
                __nv_bfloat16 h1 = __float2bfloat16(x1);
                __nv_bfloat16 h2 = __float2bfloat16(x2);
                __nv_bfloat16 h3 = __float2bfloat16(x3);
                __nv_bfloat162 ph01(h0, h1), ph23(h2, h3);
                aPh[j][2 * half]     = *(uint32_t*)&ph01;
                aPh[j][2 * half + 1] = *(uint32_t*)&ph23;
                __nv_bfloat162 pl01(__float2bfloat16(x0 - __bfloat162float(h0)),
                                    __float2bfloat16(x1 - __bfloat162float(h1)));
                __nv_bfloat162 pl23(__float2bfloat16(x2 - __bfloat162float(h2)),
                                    __float2bfloat16(x3 - __bfloat162float(h3)));
                aPl[j][2 * half]     = *(uint32_t*)&pl01;
                aPl[j][2 * half + 1] = *(uint32_t*)&pl23;
            }
        }

#pragma unroll
        for (int j = 0; j < 4; j++) {
#pragma unroll
            for (int g = 0; g < 8; g++) {
                uint32_t vh[4], vl[4];
                uint32_t baddr = vB +
                    ((j * 16 + (lane & 15)) * LDH + g * 16 + (lane >> 4) * 8) * 2;
                ldsm_x4_t(vh[0], vh[1], vh[2], vh[3], baddr);
                ldsm_x4_t(vl[0], vl[1], vl[2], vl[3], baddr + 256);
                mma_bf16(oacc[2 * g],     aPh[j], vh[0], vh[1]);
                mma_bf16(oacc[2 * g + 1], aPh[j], vh[2], vh[3]);
                mma_bf16(oacc[2 * g],     aPl[j], vh[0], vh[1]);
                mma_bf16(oacc[2 * g + 1], aPl[j], vh[2], vh[3]);
                mma_bf16(oacc[2 * g],     aPh[j], vl[0], vl[1]);
                mma_bf16(oacc[2 * g + 1], aPh[j], vl[2], vl[3]);
            }
        }
        __syncthreads();
    }

    // Epilogue: write fp16 split layout [M, 2K] = [Ch | Cl] directly.
    float inv0 = 1.0f / l0, inv1 = 1.0f / l1;
    int r0g = qbase + w * 16 + gid;
    size_t m0r = (size_t)(b * Tt + r0g) * K2Q;
    size_t m1r = (size_t)(b * Tt + r0g + 8) * K2Q;
#pragma unroll
    for (int t = 0; t < 16; t++) {
        int col = h * HD + t * 8 + tig * 2;
        float v00 = oacc[t][0] * inv0, v01 = oacc[t][1] * inv0;
        float v10 = oacc[t][2] * inv1, v11 = oacc[t][3] * inv1;
        __half h00 = __float2half(v00), h01 = __float2half(v01);
        __half h10 = __float2half(v10), h11 = __float2half(v11);
        *(__half2*)&ctxs[m0r + col]       = __half2(h00, h01);
        *(__half2*)&ctxs[m0r + DIM + col] = __half2(
            __float2half(v00 - __half2float(h00)),
            __float2half(v01 - __half2float(h01)));
        *(__half2*)&ctxs[m1r + col]       = __half2(h10, h11);
        *(__half2*)&ctxs[m1r + DIM + col] = __half2(
            __float2half(v10 - __half2float(h10)),
            __float2half(v11 - __half2float(h11)));
    }
}

// ---------------------------------------------------------------------------
// Launch
// ---------------------------------------------------------------------------
extern "C" void kernel_launch(void* const* d_in, const int* in_sizes, int n_in,
                              void* d_out, int out_size) {
    const float* x    = (const float*)d_in[0];
    const float* Wq   = (const float*)d_in[1];
    const float* Wkv  = (const float*)d_in[2];
    const float* Wo   = (const float*)d_in[3];
    const float* cosb = (const float*)d_in[4];
    const float* sinb = (const float*)d_in[5];
    float* out = (float*)d_out;

    float *qbuf, *kvbuf;
    __half *xs, *ctxs, *wqs, *wkvs, *wos;
    __nv_bfloat16 *qsb, *ksb, *vsb;
    cudaGetSymbolAddress((void**)&qbuf,   g_q);
    cudaGetSymbolAddress((void**)&kvbuf,  g_kv);
    cudaGetSymbolAddress((void**)&xs,     g_xs);
    cudaGetSymbolAddress((void**)&ctxs,   g_ctxs);
    cudaGetSymbolAddress((void**)&wqs,    g_wqs);
    cudaGetSymbolAddress((void**)&wkvs,   g_wkvs);
    cudaGetSymbolAddress((void**)&wos,    g_wos);
    cudaGetSymbolAddress((void**)&qsb,    g_qs);
    cudaGetSymbolAddress((void**)&ksb,    g_ks);
    cudaGetSymbolAddress((void**)&vsb,    g_vs);

    cudaFuncSetAttribute(hgemm256, cudaFuncAttributeMaxDynamicSharedMemorySize,
                         GEMM_SMEM);
    cudaFuncSetAttribute(flash_tc, cudaFuncAttributeMaxDynamicSharedMemorySize,
                         FLASH_SMEM);

    const int M = MROWS;  // 4096

    // Conversions
    conv_split_A<<<(M * DIM + 255) / 256, 256>>>(x, xs, M, DIM);
    conv_h<<<(DIM * DIM + 255) / 256, 256>>>(Wq, wqs, DIM * DIM);
    conv_h<<<(DIM * NKV + 255) / 256, 256>>>(Wkv, wkvs, DIM * NKV);
    conv_h<<<(DIM * DIM + 255) / 256, 256>>>(Wo, wos, DIM * DIM);

    // q = x @ Wq ; kv = x @ Wkv
    hgemm256<<<dim3(DIM / 256, M / 128), 256, GEMM_SMEM>>>(xs, wqs, qbuf, M, DIM, DIM);
    hgemm256<<<dim3(NKV / 256, M / 128), 256, GEMM_SMEM>>>(xs, wkvs, kvbuf, M, NKV, DIM);

    // fused rope + split + relayout
    {
        int total = Bb * Tt * Hh * 64 + Bb * Tt * KVH * 64 + Bb * Tt * KVH * 128;
        prep_kernel<<<(total + 255) / 256, 256>>>(qbuf, kvbuf, cosb, sinb,
                                                  qsb, ksb, vsb);
    }

    // attention -> writes ctxs split layout directly
    flash_tc<<<dim3(Tt / 64, Hh, Bb), 128, FLASH_SMEM>>>(qsb, ksb, vsb, ctxs);

    // out = ctx @ Wo
    hgemm256<<<dim3(DIM / 256, M / 128), 256, GEMM_SMEM>>>(ctxs, wos, out, M, DIM, DIM);
}

// round 13
// speedup vs baseline: 5.6555x; 1.4622x over previous
#include <cuda_runtime.h>
#include <cuda_bf16.h>
#include <cuda_fp16.h>
#include <math.h>
#include <stdint.h>

// Problem constants
#define Bb   4
#define Tt   1024
#define DIM  2048
#define Hh   16
#define KVH  4
#define Gg   4
#define HD   128

#define MROWS (Bb * Tt)          // 4096
#define NKV   (2 * KVH * HD)     // 1024

// fp32 scratch
__device__ __align__(256) float g_q  [MROWS * DIM];
__device__ __align__(256) float g_kv [MROWS * NKV];

// fp16 scratch (plain, no splits)
__device__ __align__(256) __half g_xs  [MROWS * DIM];
__device__ __align__(256) __half g_ctxs[MROWS * DIM];
__device__ __align__(256) __half g_wqs [DIM * DIM];
__device__ __align__(256) __half g_wkvs[DIM * NKV];
__device__ __align__(256) __half g_wos [DIM * DIM];

// pre-split attention operands (rope + scale applied), bf16 3-term path:
__device__ __align__(256) __nv_bfloat16 g_qs[Bb * Hh * Tt * 256];
__device__ __align__(256) __nv_bfloat16 g_ks[Bb * KVH * Tt * 256];
__device__ __align__(256) __nv_bfloat16 g_vs[Bb * KVH * Tt * 256];

// ---------------------------------------------------------------------------
// PTX helpers
// ---------------------------------------------------------------------------
__device__ __forceinline__ void ldsm_x4(uint32_t& r0, uint32_t& r1,
                                        uint32_t& r2, uint32_t& r3, uint32_t addr) {
    asm volatile("ldmatrix.sync.aligned.m8n8.x4.shared.b16 {%0,%1,%2,%3}, [%4];\n"
                 : "=r"(r0), "=r"(r1), "=r"(r2), "=r"(r3) : "r"(addr));
}
__device__ __forceinline__ void ldsm_x4_t(uint32_t& r0, uint32_t& r1,
                                          uint32_t& r2, uint32_t& r3, uint32_t addr) {
    asm volatile("ldmatrix.sync.aligned.m8n8.x4.trans.shared.b16 {%0,%1,%2,%3}, [%4];\n"
                 : "=r"(r0), "=r"(r1), "=r"(r2), "=r"(r3) : "r"(addr));
}
__device__ __forceinline__ void mma_bf16(float* c, const uint32_t* a,
                                         uint32_t b0, uint32_t b1) {
    asm volatile(
        "mma.sync.aligned.m16n8k16.row.col.f32.bf16.bf16.f32 "
        "{%0,%1,%2,%3}, {%4,%5,%6,%7}, {%8,%9}, {%0,%1,%2,%3};\n"
        : "+f"(c[0]), "+f"(c[1]), "+f"(c[2]), "+f"(c[3])
        : "r"(a[0]), "r"(a[1]), "r"(a[2]), "r"(a[3]), "r"(b0), "r"(b1));
}
__device__ __forceinline__ void mma_f16(float* c, const uint32_t* a,
                                        uint32_t b0, uint32_t b1) {
    asm volatile(
        "mma.sync.aligned.m16n8k16.row.col.f32.f16.f16.f32 "
        "{%0,%1,%2,%3}, {%4,%5,%6,%7}, {%8,%9}, {%0,%1,%2,%3};\n"
        : "+f"(c[0]), "+f"(c[1]), "+f"(c[2]), "+f"(c[3])
        : "r"(a[0]), "r"(a[1]), "r"(a[2]), "r"(a[3]), "r"(b0), "r"(b1));
}
#define CP_ASYNC16(dst, src) \
    asm volatile("cp.async.cg.shared.global [%0], [%1], 16;\n" :: "r"(dst), "l"(src))
#define CP_COMMIT() asm volatile("cp.async.commit_group;\n" ::: "memory")
template <int N>
__device__ __forceinline__ void cp_wait() {
    asm volatile("cp.async.wait_group %0;\n" :: "n"(N) : "memory");
}

// ---------------------------------------------------------------------------
// Conversion kernel (fp32 -> fp16, vectorized)
// ---------------------------------------------------------------------------
__global__ void conv_h(const float* __restrict__ in,
                       __half* __restrict__ out, int n) {
    int idx = blockIdx.x * blockDim.x + threadIdx.x;
    int i4 = idx * 4;
    if (i4 >= n) return;
    float4 v = *(const float4*)&in[i4];
    __half2 a = __floats2half2_rn(v.x, v.y);
    __half2 b = __floats2half2_rn(v.z, v.w);
    *(__half2*)&out[i4]     = a;
    *(__half2*)&out[i4 + 2] = b;
}

// ---------------------------------------------------------------------------
// fp16 TC GEMM: C[M,N] f32 = A[M,K] h @ B[K,N] h
// 128x256 CTA tile, BK=32, 4-stage cp.async (wait_group 2), 8 warps 64x64.
// ---------------------------------------------------------------------------
#define LDA 40    // halfs per A smem row (32 + 8)
#define LDB 264   // halfs per B smem row (256 + 8)
#define GSTAGES 4
#define G_ASZ (128 * LDA * 2)
#define G_BSZ (32 * LDB * 2)
#define G_STG (G_ASZ + G_BSZ)
#define GEMM_SMEM (GSTAGES * G_STG)

__global__ __launch_bounds__(256, 1) void hgemm256(const __half* __restrict__ A,
                                                   const __half* __restrict__ B,
                                                   float* __restrict__ C,
                                                   int M, int N, int K) {
    extern __shared__ __half gsm[];

    const int tid  = threadIdx.x;
    const int lane = tid & 31;
    const int w    = tid >> 5;
    const int wm   = (w & 1) * 64;
    const int wn   = (w >> 1) * 64;
    const int rowBase = blockIdx.y * 128;
    const int colBase = blockIdx.x * 256;

    const uint32_t S0 = (uint32_t)__cvta_generic_to_shared(gsm);

    float acc[4][8][4];
#pragma unroll
    for (int mi = 0; mi < 4; mi++)
#pragma unroll
        for (int ni = 0; ni < 8; ni++)
#pragma unroll
            for (int r = 0; r < 4; r++) acc[mi][ni][r] = 0.0f;

    const int NI = K / 32;

    auto load_stage = [&](int it, int s) {
        int k0 = it * 32;
        const uint32_t aB = S0 + s * G_STG;
        const uint32_t bB = aB + G_ASZ;
#pragma unroll
        for (int c = 0; c < 2; c++) {               // A: 512 chunks of 16B
            int i = tid + c * 256;
            int row = i >> 2, cc = (i & 3) * 8;
            const __half* src = A + (size_t)(rowBase + row) * K + k0 + cc;
            CP_ASYNC16(aB + (row * LDA + cc) * 2, src);
        }
#pragma unroll
        for (int c = 0; c < 4; c++) {               // B: 1024 chunks
            int i = tid + c * 256;
            int row = i >> 5, cc = (i & 31) * 8;
            const __half* src = B + (size_t)(k0 + row) * N + colBase + cc;
            CP_ASYNC16(bB + (row * LDB + cc) * 2, src);
        }
        CP_COMMIT();
    };

    load_stage(0, 0);
    load_stage(1, 1);
    load_stage(2, 2);

    for (int it = 0; it < NI; ++it) {
        cp_wait<2>();
        __syncthreads();
        if (it + 3 < NI) load_stage(it + 3, (it + 3) & 3);
        else CP_COMMIT();

        const int s = it & 3;
        const uint32_t aB = S0 + s * G_STG;
        const uint32_t bB = aB + G_ASZ;

#pragma unroll
        for (int ks = 0; ks < 32; ks += 16) {
            uint32_t ra[4][4], rb[4][4];
#pragma unroll
            for (int mi = 0; mi < 4; mi++) {
                uint32_t addr = aB +
                    ((wm + mi * 16 + (lane & 15)) * LDA + ks + (lane >> 4) * 8) * 2;
                ldsm_x4(ra[mi][0], ra[mi][1], ra[mi][2], ra[mi][3], addr);
            }
#pragma unroll
            for (int g = 0; g < 4; g++) {
                uint32_t addr = bB +
                    ((ks + (lane & 15)) * LDB + wn + g * 16 + (lane >> 4) * 8) * 2;
                ldsm_x4_t(rb[g][0], rb[g][1], rb[g][2], rb[g][3], addr);
            }
#pragma unroll
            for (int mi = 0; mi < 4; mi++)
#pragma unroll
                for (int ni = 0; ni < 8; ni++)
                    mma_f16(acc[mi][ni], ra[mi],
                            rb[ni >> 1][(ni & 1) * 2], rb[ni >> 1][(ni & 1) * 2 + 1]);
        }
    }

#pragma unroll
    for (int mi = 0; mi < 4; mi++)
#pragma unroll
        for (int ni = 0; ni < 8; ni++) {
            int r = rowBase + wm + mi * 16 + (lane >> 2);
            int cc = colBase + wn + ni * 8 + (lane & 3) * 2;
            *(float2*)&C[(size_t)r * N + cc] =
                make_float2(acc[mi][ni][0], acc[mi][ni][1]);
            *(float2*)&C[(size_t)(r + 8) * N + cc] =
                make_float2(acc[mi][ni][2], acc[mi][ni][3]);
        }
}

// ---------------------------------------------------------------------------
// Fused prep: RoPE + scale + compensated bf16 split + head-major relayout.
// ---------------------------------------------------------------------------
__global__ void prep_kernel(const float* __restrict__ q,
                            const float* __restrict__ kvb,
                            const float* __restrict__ cosb,
                            const float* __restrict__ sinb,
                            __nv_bfloat16* __restrict__ qs,
                            __nv_bfloat16* __restrict__ ks,
                            __nv_bfloat16* __restrict__ vs) {
    const int NQ = Bb * Tt * Hh * 64;
    const int NK = Bb * Tt * KVH * 64;
    const int NV = Bb * Tt * KVH * 128;
    const float scale = 0.08838834764831845f;
    int idx = blockIdx.x * blockDim.x + threadIdx.x;
    if (idx < NQ) {
        int d = idx & 63;
        int h = (idx >> 6) & 15;
        int t = (idx >> 10) & 1023;
        int b = idx >> 20;
        float c = cosb[t * 64 + d];
        float s = sinb[t * 64 + d];
        size_t src = ((size_t)(b * Tt + t) * Hh + h) * HD;
        float u1 = q[src + d], u2 = q[src + 64 + d];
        float r1 = (u1 * c - u2 * s) * scale;
        float r2 = (u1 * s + u2 * c) * scale;
        __nv_bfloat16 h1 = __float2bfloat16(r1);
        __nv_bfloat16 h2 = __float2bfloat16(r2);
        size_t dst = ((size_t)(b * Hh + h) * Tt + t) * 256;
        qs[dst + d]        = h1;
        qs[dst + 128 + d]  = __float2bfloat16(r1 - __bfloat162float(h1));
        qs[dst + 64 + d]   = h2;
        qs[dst + 192 + d]  = __float2bfloat16(r2 - __bfloat162float(h2));
    } else if (idx < NQ + NK) {
        int j = idx - NQ;
        int d = j & 63;
        int kvh = (j >> 6) & 3;
        int t = (j >> 8) & 1023;
        int b = j >> 18;
        float c = cosb[t * 64 + d];
        float s = sinb[t * 64 + d];
        size_t src = ((size_t)(b * Tt + t) * 2) * (KVH * HD) + kvh * HD;
        float u1 = kvb[src + d], u2 = kvb[src + 64 + d];
        float r1 = u1 * c - u2 * s;
        float r2 = u1 * s + u2 * c;
        __nv_bfloat16 h1 = __float2bfloat16(r1);
        __nv_bfloat16 h2 = __float2bfloat16(r2);
        size_t dst = ((size_t)(b * KVH + kvh) * Tt + t) * 256;
        ks[dst + d]        = h1;
        ks[dst + 128 + d]  = __float2bfloat16(r1 - __bfloat162float(h1));
        ks[dst + 64 + d]   = h2;
        ks[dst + 192 + d]  = __float2bfloat16(r2 - __bfloat162float(h2));
    } else if (idx < NQ + NK + NV) {
        int j = idx - NQ - NK;
        int d = j & 127;
        int kvh = (j >> 7) & 3;
        int t = (j >> 9) & 1023;
        int b = j >> 19;
        size_t src = ((size_t)(b * Tt + t) * 2 + 1) * (KVH * HD) + kvh * HD;
        float u = kvb[src + d];
        __nv_bfloat16 hh = __float2bfloat16(u);
        size_t dst = ((size_t)(b * KVH + kvh) * Tt + t) * 256;
        vs[dst + d]       = hh;
        vs[dst + 128 + d] = __float2bfloat16(u - __bfloat162float(hh));
    }
}

// ---------------------------------------------------------------------------
// Tensor-core flash attention (bf16 3-term), cp.async double-buffered K/V.
// Epilogue writes plain fp16 ctx [M, DIM].
// ---------------------------------------------------------------------------
#define LDH 264
#define F_QSZ (64 * LDH * 2)
#define F_STG (64 * LDH * 2)
#define FLASH_SMEM (F_QSZ + 4 * F_STG)   // Q + 2xK + 2xV

__global__ __launch_bounds__(128, 1) void flash_tc(const __nv_bfloat16* __restrict__ qs,
                                                   const __nv_bfloat16* __restrict__ ks,
                                                   const __nv_bfloat16* __restrict__ vs,
                                                   __half* __restrict__ ctxs) {
    extern __shared__ __nv_bfloat16 fsm[];

    const int qtile = blockIdx.x;
    const int h     = blockIdx.y;
    const int b     = blockIdx.z;
    const int kvh   = h >> 2;
    const int qbase = qtile * 64;

    const int tid  = threadIdx.x;
    const int lane = tid & 31;
    const int w    = tid >> 5;
    const int gid  = lane >> 2;
    const int tig  = lane & 3;

    const uint32_t QsA = (uint32_t)__cvta_generic_to_shared(fsm);
    const uint32_t KsA = QsA + F_QSZ;
    const uint32_t VsA = KsA + 2 * F_STG;

    {
        const __nv_bfloat16* qsrc = qs + ((size_t)(b * Hh + h) * Tt + qbase) * 256;
#pragma unroll
        for (int i = 0; i < 16; i++) {
            int c = tid + i * 128;
            int r = c >> 5, cc = (c & 31) * 8;
            CP_ASYNC16(QsA + (r * LDH + cc) * 2, qsrc + r * 256 + cc);
        }
        CP_COMMIT();
    }

    auto load_kv = [&](int kt, int s) {
        const __nv_bfloat16* kb = ks + ((size_t)(b * KVH + kvh) * Tt + kt * 64) * 256;
        const __nv_bfloat16* vb = vs + ((size_t)(b * KVH + kvh) * Tt + kt * 64) * 256;
        const uint32_t kd = KsA + s * F_STG;
        const uint32_t vd = VsA + s * F_STG;
#pragma unroll
        for (int i = 0; i < 16; i++) {
            int c = tid + i * 128;
            int r = c >> 5, cc = (c & 31) * 8;
            CP_ASYNC16(kd + (r * LDH + cc) * 2, kb + r * 256 + cc);
        }
#pragma unroll
        for (int i = 0; i < 16; i++) {
            int c = tid + i * 128;
            int r = c >> 5, cc = (c & 31) * 8;
            CP_ASYNC16(vd + (r * LDH + cc) * 2, vb + r * 256 + cc);
        }
        CP_COMMIT();
    };

    load_kv(0, 0);

    float oacc[16][4];
#pragma unroll
    for (int t = 0; t < 16; t++)
#pragma unroll
        for (int r = 0; r < 4; r++) oacc[t][r] = 0.0f;
    float m0 = -INFINITY, m1 = -INFINITY, l0 = 0.0f, l1 = 0.0f;

    for (int kt = 0; kt <= qtile; ++kt) {
        if (kt < qtile) load_kv(kt + 1, (kt + 1) & 1);
        else CP_COMMIT();
        cp_wait<1>();
        __syncthreads();

        const uint32_t kB = KsA + (kt & 1) * F_STG;
        const uint32_t vB = VsA + (kt & 1) * F_STG;

        float sacc[8][4];
#pragma unroll
        for (int t = 0; t < 8; t++)
#pragma unroll
            for (int r = 0; r < 4; r++) sacc[t][r] = 0.0f;

#pragma unroll
        for (int kc = 0; kc < 8; kc++) {
            uint32_t qh[4], ql[4];
            uint32_t aaddr = QsA +
                ((w * 16 + (lane & 15)) * LDH + kc * 16 + (lane >> 4) * 8) * 2;
            ldsm_x4(qh[0], qh[1], qh[2], qh[3], aaddr);
            ldsm_x4(ql[0], ql[1], ql[2], ql[3], aaddr + 256);
#pragma unroll
            for (int g = 0; g < 4; g++) {
                uint32_t kh[4], kl[4];
                uint32_t baddr = kB +
                    ((g * 16 + (lane & 15)) * LDH + kc * 16 + (lane >> 4) * 8) * 2;
                ldsm_x4(kh[0], kh[1], kh[2], kh[3], baddr);
                ldsm_x4(kl[0], kl[1], kl[2], kl[3], baddr + 256);
                mma_bf16(sacc[2 * g],     qh, kh[0], kh[2]);
                mma_bf16(sacc[2 * g + 1], qh, kh[1], kh[3]);
                mma_bf16(sacc[2 * g],     qh, kl[0], kl[2]);
                mma_bf16(sacc[2 * g + 1], qh, kl[1], kl[3]);
                mma_bf16(sacc[2 * g],     ql, kh[0], kh[2]);
                mma_bf16(sacc[2 * g + 1], ql, kh[1], kh[3]);
            }
        }

        if (kt == qtile) {
            int row0 = w * 16 + gid;
#pragma unroll
            for (int s8 = 0; s8 < 8; s8++) {
                int cb = s8 * 8 + tig * 2;
                if (cb     > row0)     sacc[s8][0] = -INFINITY;
                if (cb + 1 > row0)     sacc[s8][1] = -INFINITY;
                if (cb     > row0 + 8) sacc[s8][2] = -INFINITY;
                if (cb + 1 > row0 + 8) sacc[s8][3] = -INFINITY;
            }
        }

        float mx0 = -INFINITY, mx1 = -INFINITY;
#pragma unroll
        for (int s8 = 0; s8 < 8; s8++) {
            mx0 = fmaxf(mx0, fmaxf(sacc[s8][0], sacc[s8][1]));
            mx1 = fmaxf(mx1, fmaxf(sacc[s8][2], sacc[s8][3]));
        }
#pragma unroll
        for (int o = 1; o < 4; o <<= 1) {
            mx0 = fmaxf(mx0, __shfl_xor_sync(0xffffffffu, mx0, o));
            mx1 = fmaxf(mx1, __shfl_xor_sync(0xffffffffu, mx1, o));
        }
        float mn0 = fmaxf(m0, mx0), mn1 = fmaxf(m1, mx1);
        float f0 = __expf(m0 - mn0), f1 = __expf(m1 - mn1);
        float rs0 = 0.0f, rs1 = 0.0f;
#pragma unroll
        for (int s8 = 0; s8 < 8; s8++) {
            sacc[s8][0] = __expf(sacc[s8][0] - mn0);
            sacc[s8][1] = __expf(sacc[s8][1] - mn0);
            sacc[s8][2] = __expf(sacc[s8][2] - mn1);
            sacc[s8][3] = __expf(sacc[s8][3] - mn1);
            rs0 += sacc[s8][0] + sacc[s8][1];
            rs1 += sacc[s8][2] + sacc[s8][3];
        }
#pragma unroll
        for (int o = 1; o < 4; o <<= 1) {
            rs0 += __shfl_xor_sync(0xffffffffu, rs0, o);
            rs1 += __shfl_xor_sync(0xffffffffu, rs1, o);
        }
        l0 = l0 * f0 + rs0; m0 = mn0;
        l1 = l1 * f1 + rs1; m1 = mn1;
#pragma unroll
        for (int t = 0; t < 16; t++) {
            oacc[t][0] *= f0; oacc[t][1] *= f0;
            oacc[t][2] *= f1; oacc[t][3] *= f1;
        }

        uint32_t aPh[4][4], aPl[4][4];
#pragma unroll
        for (int j = 0; j < 4; j++) {
#pragma unroll
            for (int half = 0; half < 2; half++) {
                int t = 2 * j + half;
                float x0 = sacc[t][0], x1 = sacc[t][1];
                float x2 = sacc[t][2], x3 = sacc[t][3];
                __nv_bfloat16 h0 = __float2bfloat16(x0);
                __nv_bfloat16 h1 = __float2bfloat16(x1);
                __nv_bfloat16 h2 = __float2bfloat16(x2);
                __nv_bfloat16 h3 = __float2bfloat16(x3);
                __nv_bfloat162 ph01(h0, h1), ph23(h2, h3);
                aPh[j][2 * half]     = *(uint32_t*)&ph01;
                aPh[j][2 * half + 1] = *(uint32_t*)&ph23;
                __nv_bfloat162 pl01(__float2bfloat16(x0 - __bfloat162float(h0)),
                                    __float2bfloat16(x1 - __bfloat162float(h1)));
                __nv_bfloat162 pl23(__float2bfloat16(x2 - __bfloat162float(h2)),
                                    __float2bfloat16(x3 - __bfloat162float(h3)));
                aPl[j][2 * half]     = *(uint32_t*)&pl01;
                aPl[j][2 * half + 1] = *(uint32_t*)&pl23;
            }
        }

#pragma unroll
        for (int j = 0; j < 4; j++) {
#pragma unroll
            for (int g = 0; g < 8; g++) {
                uint32_t vh[4], vl[4];
                uint32_t baddr = vB +
                    ((j * 16 + (lane & 15)) * LDH + g * 16 + (lane >> 4) * 8) * 2;
                ldsm_x4_t(vh[0], vh[1], vh[2], vh[3], baddr);
                ldsm_x4_t(vl[0], vl[1], vl[2], vl[3], baddr + 256);
                mma_bf16(oacc[2 * g],     aPh[j], vh[0], vh[1]);
                mma_bf16(oacc[2 * g + 1], aPh[j], vh[2], vh[3]);
                mma_bf16(oacc[2 * g],     aPl[j], vh[0], vh[1]);
                mma_bf16(oacc[2 * g + 1], aPl[j], vh[2], vh[3]);
                mma_bf16(oacc[2 * g],     aPh[j], vl[0], vl[1]);
                mma_bf16(oacc[2 * g + 1], aPh[j], vl[2], vl[3]);
            }
        }
        __syncthreads();
    }

    // Epilogue: write plain fp16 ctx [M, DIM].
    float inv0 = 1.0f / l0, inv1 = 1.0f / l1;
    int r0g = qbase + w * 16 + gid;
    size_t m0r = (size_t)(b * Tt + r0g) * DIM;
    size_t m1r = (size_t)(b * Tt + r0g + 8) * DIM;
#pragma unroll
    for (int t = 0; t < 16; t++) {
        int col = h * HD + t * 8 + tig * 2;
        *(__half2*)&ctxs[m0r + col] =
            __floats2half2_rn(oacc[t][0] * inv0, oacc[t][1] * inv0);
        *(__half2*)&ctxs[m1r + col] =
            __floats2half2_rn(oacc[t][2] * inv1, oacc[t][3] * inv1);
    }
}

// ---------------------------------------------------------------------------
// Launch
// ---------------------------------------------------------------------------
extern "C" void kernel_launch(void* const* d_in, const int* in_sizes, int n_in,
                              void* d_out, int out_size) {
    const float* x    = (const float*)d_in[0];
    const float* Wq   = (const float*)d_in[1];
    const float* Wkv  = (const float*)d_in[2];
    const float* Wo   = (const float*)d_in[3];
    const float* cosb = (const float*)d_in[4];
    const float* sinb = (const float*)d_in[5];
    float* out = (float*)d_out;

    float *qbuf, *kvbuf;
    __half *xs, *ctxs, *wqs, *wkvs, *wos;
    __nv_bfloat16 *qsb, *ksb, *vsb;
    cudaGetSymbolAddress((void**)&qbuf,   g_q);
    cudaGetSymbolAddress((void**)&kvbuf,  g_kv);
    cudaGetSymbolAddress((void**)&xs,     g_xs);
    cudaGetSymbolAddress((void**)&ctxs,   g_ctxs);
    cudaGetSymbolAddress((void**)&wqs,    g_wqs);
    cudaGetSymbolAddress((void**)&wkvs,   g_wkvs);
    cudaGetSymbolAddress((void**)&wos,    g_wos);
    cudaGetSymbolAddress((void**)&qsb,    g_qs);
    cudaGetSymbolAddress((void**)&ksb,    g_ks);
    cudaGetSymbolAddress((void**)&vsb,    g_vs);

    cudaFuncSetAttribute(hgemm256, cudaFuncAttributeMaxDynamicSharedMemorySize,
                         GEMM_SMEM);
    cudaFuncSetAttribute(flash_tc, cudaFuncAttributeMaxDynamicSharedMemorySize,
                         FLASH_SMEM);

    const int M = MROWS;  // 4096

    // Conversions (all plain fp16)
    conv_h<<<(M * DIM / 4 + 255) / 256, 256>>>(x, xs, M * DIM);
    conv_h<<<(DIM * DIM / 4 + 255) / 256, 256>>>(Wq, wqs, DIM * DIM);
    conv_h<<<(DIM * NKV / 4 + 255) / 256, 256>>>(Wkv, wkvs, DIM * NKV);
    conv_h<<<(DIM * DIM / 4 + 255) / 256, 256>>>(Wo, wos, DIM * DIM);

    // q = x @ Wq ; kv = x @ Wkv
    hgemm256<<<dim3(DIM / 256, M / 128), 256, GEMM_SMEM>>>(xs, wqs, qbuf, M, DIM, DIM);
    hgemm256<<<dim3(NKV / 256, M / 128), 256, GEMM_SMEM>>>(xs, wkvs, kvbuf, M, NKV, DIM);

    // fused rope + split + relayout
    {
        int total = Bb * Tt * Hh * 64 + Bb * Tt * KVH * 64 + Bb * Tt * KVH * 128;
        prep_kernel<<<(total + 255) / 256, 256>>>(qbuf, kvbuf, cosb, sinb,
                                                  qsb, ksb, vsb);
    }

    // attention -> plain fp16 ctx
    flash_tc<<<dim3(Tt / 64, Hh, Bb), 128, FLASH_SMEM>>>(qsb, ksb, vsb, ctxs);

    // out = ctx @ Wo
    hgemm256<<<dim3(DIM / 256, M / 128), 256, GEMM_SMEM>>>(ctxs, wos, out, M, DIM, DIM);
}

// round 15
// speedup vs baseline: 6.9562x; 1.2300x over previous
#include <cuda_runtime.h>
#include <cuda_bf16.h>
#include <cuda_fp16.h>
#include <math.h>
#include <stdint.h>

// Problem constants
#define Bb   4
#define Tt   1024
#define DIM  2048
#define Hh   16
#define KVH  4
#define Gg   4
#define HD   128

#define MROWS (Bb * Tt)          // 4096
#define NKV   (2 * KVH * HD)     // 1024

// fp32 scratch
__device__ __align__(256) float g_q  [MROWS * DIM];
__device__ __align__(256) float g_kv [MROWS * NKV];

// fp16 scratch (plain, no splits)
__device__ __align__(256) __half g_xs  [MROWS * DIM];
__device__ __align__(256) __half g_ctxs[MROWS * DIM];
__device__ __align__(256) __half g_wqs [DIM * DIM];
__device__ __align__(256) __half g_wkvs[DIM * NKV];
__device__ __align__(256) __half g_wos [DIM * DIM];

// fp16 attention operands (rope + scale applied), head-major:
// g_qs16: (B,H,T,128), g_ks16/g_vs16: (B,KVH,T,128)
__device__ __align__(256) __half g_qs16[Bb * Hh * Tt * HD];
__device__ __align__(256) __half g_ks16[Bb * KVH * Tt * HD];
__device__ __align__(256) __half g_vs16[Bb * KVH * Tt * HD];

// ---------------------------------------------------------------------------
// PTX helpers
// ---------------------------------------------------------------------------
__device__ __forceinline__ void ldsm_x4(uint32_t& r0, uint32_t& r1,
                                        uint32_t& r2, uint32_t& r3, uint32_t addr) {
    asm volatile("ldmatrix.sync.aligned.m8n8.x4.shared.b16 {%0,%1,%2,%3}, [%4];\n"
                 : "=r"(r0), "=r"(r1), "=r"(r2), "=r"(r3) : "r"(addr));
}
__device__ __forceinline__ void ldsm_x4_t(uint32_t& r0, uint32_t& r1,
                                          uint32_t& r2, uint32_t& r3, uint32_t addr) {
    asm volatile("ldmatrix.sync.aligned.m8n8.x4.trans.shared.b16 {%0,%1,%2,%3}, [%4];\n"
                 : "=r"(r0), "=r"(r1), "=r"(r2), "=r"(r3) : "r"(addr));
}
__device__ __forceinline__ void mma_f16(float* c, const uint32_t* a,
                                        uint32_t b0, uint32_t b1) {
    asm volatile(
        "mma.sync.aligned.m16n8k16.row.col.f32.f16.f16.f32 "
        "{%0,%1,%2,%3}, {%4,%5,%6,%7}, {%8,%9}, {%0,%1,%2,%3};\n"
        : "+f"(c[0]), "+f"(c[1]), "+f"(c[2]), "+f"(c[3])
        : "r"(a[0]), "r"(a[1]), "r"(a[2]), "r"(a[3]), "r"(b0), "r"(b1));
}
#define CP_ASYNC16(dst, src) \
    asm volatile("cp.async.cg.shared.global [%0], [%1], 16;\n" :: "r"(dst), "l"(src))
#define CP_COMMIT() asm volatile("cp.async.commit_group;\n" ::: "memory")
template <int N>
__device__ __forceinline__ void cp_wait() {
    asm volatile("cp.async.wait_group %0;\n" :: "n"(N) : "memory");
}

// ---------------------------------------------------------------------------
// Conversion kernel (fp32 -> fp16, vectorized)
// ---------------------------------------------------------------------------
__global__ void conv_h(const float* __restrict__ in,
                       __half* __restrict__ out, int n) {
    int idx = blockIdx.x * blockDim.x + threadIdx.x;
    int i4 = idx * 4;
    if (i4 >= n) return;
    float4 v = *(const float4*)&in[i4];
    *(__half2*)&out[i4]     = __floats2half2_rn(v.x, v.y);
    *(__half2*)&out[i4 + 2] = __floats2half2_rn(v.z, v.w);
}

// ---------------------------------------------------------------------------
// fp16 TC GEMM: C[M,N] f32 = A[M,K] h @ B[K,N] h
// 128x256 CTA tile, BK=32, 4-stage cp.async (wait_group 2), 8 warps 64x64.
// ---------------------------------------------------------------------------
#define LDA 40    // halfs per A smem row (32 + 8)
#define LDB 264   // halfs per B smem row (256 + 8)
#define GSTAGES 4
#define G_ASZ (128 * LDA * 2)
#define G_BSZ (32 * LDB * 2)
#define G_STG (G_ASZ + G_BSZ)
#define GEMM_SMEM (GSTAGES * G_STG)

__global__ __launch_bounds__(256, 1) void hgemm256(const __half* __restrict__ A,
                                                   const __half* __restrict__ B,
                                                   float* __restrict__ C,
                                                   int M, int N, int K) {
    extern __shared__ __half gsm[];

    const int tid  = threadIdx.x;
    const int lane = tid & 31;
    const int w    = tid >> 5;
    const int wm   = (w & 1) * 64;
    const int wn   = (w >> 1) * 64;
    const int rowBase = blockIdx.y * 128;
    const int colBase = blockIdx.x * 256;

    const uint32_t S0 = (uint32_t)__cvta_generic_to_shared(gsm);

    float acc[4][8][4];
#pragma unroll
    for (int mi = 0; mi < 4; mi++)
#pragma unroll
        for (int ni = 0; ni < 8; ni++)
#pragma unroll
            for (int r = 0; r < 4; r++) acc[mi][ni][r] = 0.0f;

    const int NI = K / 32;

    auto load_stage = [&](int it, int s) {
        int k0 = it * 32;
        const uint32_t aB = S0 + s * G_STG;
        const uint32_t bB = aB + G_ASZ;
#pragma unroll
        for (int c = 0; c < 2; c++) {               // A: 512 chunks of 16B
            int i = tid + c * 256;
            int row = i >> 2, cc = (i & 3) * 8;
            const __half* src = A + (size_t)(rowBase + row) * K + k0 + cc;
            CP_ASYNC16(aB + (row * LDA + cc) * 2, src);
        }
#pragma unroll
        for (int c = 0; c < 4; c++) {               // B: 1024 chunks
            int i = tid + c * 256;
            int row = i >> 5, cc = (i & 31) * 8;
            const __half* src = B + (size_t)(k0 + row) * N + colBase + cc;
            CP_ASYNC16(bB + (row * LDB + cc) * 2, src);
        }
        CP_COMMIT();
    };

    load_stage(0, 0);
    load_stage(1, 1);
    load_stage(2, 2);

    for (int it = 0; it < NI; ++it) {
        cp_wait<2>();
        __syncthreads();
        if (it + 3 < NI) load_stage(it + 3, (it + 3) & 3);
        else CP_COMMIT();

        const int s = it & 3;
        const uint32_t aB = S0 + s * G_STG;
        const uint32_t bB = aB + G_ASZ;

#pragma unroll
        for (int ks = 0; ks < 32; ks += 16) {
            uint32_t ra[4][4], rb[4][4];
#pragma unroll
            for (int mi = 0; mi < 4; mi++) {
                uint32_t addr = aB +
                    ((wm + mi * 16 + (lane & 15)) * LDA + ks + (lane >> 4) * 8) * 2;
                ldsm_x4(ra[mi][0], ra[mi][1], ra[mi][2], ra[mi][3], addr);
            }
#pragma unroll
            for (int g = 0; g < 4; g++) {
                uint32_t addr = bB +
                    ((ks + (lane & 15)) * LDB + wn + g * 16 + (lane >> 4) * 8) * 2;
                ldsm_x4_t(rb[g][0], rb[g][1], rb[g][2], rb[g][3], addr);
            }
#pragma unroll
            for (int mi = 0; mi < 4; mi++)
#pragma unroll
                for (int ni = 0; ni < 8; ni++)
                    mma_f16(acc[mi][ni], ra[mi],
                            rb[ni >> 1][(ni & 1) * 2], rb[ni >> 1][(ni & 1) * 2 + 1]);
        }
    }

#pragma unroll
    for (int mi = 0; mi < 4; mi++)
#pragma unroll
        for (int ni = 0; ni < 8; ni++) {
            int r = rowBase + wm + mi * 16 + (lane >> 2);
            int cc = colBase + wn + ni * 8 + (lane & 3) * 2;
            *(float2*)&C[(size_t)r * N + cc] =
                make_float2(acc[mi][ni][0], acc[mi][ni][1]);
            *(float2*)&C[(size_t)(r + 8) * N + cc] =
                make_float2(acc[mi][ni][2], acc[mi][ni][3]);
        }
}

// ---------------------------------------------------------------------------
// Fused prep: RoPE + scale + fp16 convert + head-major relayout.
// ---------------------------------------------------------------------------
__global__ void prep_kernel(const float* __restrict__ q,
                            const float* __restrict__ kvb,
                            const float* __restrict__ cosb,
                            const float* __restrict__ sinb,
                            __half* __restrict__ qs,
                            __half* __restrict__ ks,
                            __half* __restrict__ vs) {
    const int NQ = Bb * Tt * Hh * 64;
    const int NK = Bb * Tt * KVH * 64;
    const int NV = Bb * Tt * KVH * 128;
    const float scale = 0.08838834764831845f;
    int idx = blockIdx.x * blockDim.x + threadIdx.x;
    if (idx < NQ) {
        int d = idx & 63;
        int h = (idx >> 6) & 15;
        int t = (idx >> 10) & 1023;
        int b = idx >> 20;
        float c = cosb[t * 64 + d];
        float s = sinb[t * 64 + d];
        size_t src = ((size_t)(b * Tt + t) * Hh + h) * HD;
        float u1 = q[src + d], u2 = q[src + 64 + d];
        size_t dst = ((size_t)(b * Hh + h) * Tt + t) * HD;
        qs[dst + d]      = __float2half((u1 * c - u2 * s) * scale);
        qs[dst + 64 + d] = __float2half((u1 * s + u2 * c) * scale);
    } else if (idx < NQ + NK) {
        int j = idx - NQ;
        int d = j & 63;
        int kvh = (j >> 6) & 3;
        int t = (j >> 8) & 1023;
        int b = j >> 18;
        float c = cosb[t * 64 + d];
        float s = sinb[t * 64 + d];
        size_t src = ((size_t)(b * Tt + t) * 2) * (KVH * HD) + kvh * HD;
        float u1 = kvb[src + d], u2 = kvb[src + 64 + d];
        size_t dst = ((size_t)(b * KVH + kvh) * Tt + t) * HD;
        ks[dst + d]      = __float2half(u1 * c - u2 * s);
        ks[dst + 64 + d] = __float2half(u1 * s + u2 * c);
    } else if (idx < NQ + NK + NV) {
        int j = idx - NQ - NK;
        int d = j & 127;
        int kvh = (j >> 7) & 3;
        int t = (j >> 9) & 1023;
        int b = j >> 19;
        size_t src = ((size_t)(b * Tt + t) * 2 + 1) * (KVH * HD) + kvh * HD;
        size_t dst = ((size_t)(b * KVH + kvh) * Tt + t) * HD;
        vs[dst + d] = __float2half(kvb[src + d]);
    }
}

// ---------------------------------------------------------------------------
// Tensor-core flash attention, plain fp16, cp.async double-buffered K/V.
// CTA: 64 q rows of one (b,h). 128 threads = 4 warps.
// ---------------------------------------------------------------------------
#define LDH2 136                      // halfs per row (128 + 8 pad)
#define F2_TILE (64 * LDH2 * 2)       // bytes per 64-row tile
#define FLASH_SMEM (5 * F2_TILE)      // Q + 2xK + 2xV  (~87 KB)

__global__ __launch_bounds__(128) void flash_tc(const __half* __restrict__ qs,
                                                const __half* __restrict__ ks,
                                                const __half* __restrict__ vs,
                                                __half* __restrict__ ctxs) {
    extern __shared__ __half fsm[];

    const int qtile = blockIdx.x;
    const int h     = blockIdx.y;
    const int b     = blockIdx.z;
    const int kvh   = h >> 2;
    const int qbase = qtile * 64;

    const int tid  = threadIdx.x;
    const int lane = tid & 31;
    const int w    = tid >> 5;
    const int gid  = lane >> 2;
    const int tig  = lane & 3;

    const uint32_t QsA = (uint32_t)__cvta_generic_to_shared(fsm);
    const uint32_t KsA = QsA + F2_TILE;
    const uint32_t VsA = KsA + 2 * F2_TILE;

    // Q load: 64 rows x 16 chunks of 16B = 1024 chunks, 8 per thread
    {
        const __half* qsrc = qs + ((size_t)(b * Hh + h) * Tt + qbase) * HD;
#pragma unroll
        for (int i = 0; i < 8; i++) {
            int c = tid + i * 128;
            int r = c >> 4, cc = (c & 15) * 8;
            CP_ASYNC16(QsA + (r * LDH2 + cc) * 2, qsrc + r * HD + cc);
        }
        CP_COMMIT();
    }

    auto load_kv = [&](int kt, int s) {
        const __half* kb = ks + ((size_t)(b * KVH + kvh) * Tt + kt * 64) * HD;
        const __half* vb = vs + ((size_t)(b * KVH + kvh) * Tt + kt * 64) * HD;
        const uint32_t kd = KsA + s * F2_TILE;
        const uint32_t vd = VsA + s * F2_TILE;
#pragma unroll
        for (int i = 0; i < 8; i++) {
            int c = tid + i * 128;
            int r = c >> 4, cc = (c & 15) * 8;
            CP_ASYNC16(kd + (r * LDH2 + cc) * 2, kb + r * HD + cc);
        }
#pragma unroll
        for (int i = 0; i < 8; i++) {
            int c = tid + i * 128;
            int r = c >> 4, cc = (c & 15) * 8;
            CP_ASYNC16(vd + (r * LDH2 + cc) * 2, vb + r * HD + cc);
        }
        CP_COMMIT();
    };

    load_kv(0, 0);

    float oacc[16][4];
#pragma unroll
    for (int t = 0; t < 16; t++)
#pragma unroll
        for (int r = 0; r < 4; r++) oacc[t][r] = 0.0f;
    float m0 = -INFINITY, m1 = -INFINITY, l0 = 0.0f, l1 = 0.0f;

    for (int kt = 0; kt <= qtile; ++kt) {
        if (kt < qtile) load_kv(kt + 1, (kt + 1) & 1);
        else CP_COMMIT();
        cp_wait<1>();
        __syncthreads();

        const uint32_t kB = KsA + (kt & 1) * F2_TILE;
        const uint32_t vB = VsA + (kt & 1) * F2_TILE;

        // S = Q K^T (fp16, single term)
        float sacc[8][4];
#pragma unroll
        for (int t = 0; t < 8; t++)
#pragma unroll
            for (int r = 0; r < 4; r++) sacc[t][r] = 0.0f;

#pragma unroll
        for (int kc = 0; kc < 8; kc++) {
            uint32_t qf[4];
            uint32_t aaddr = QsA +
                ((w * 16 + (lane & 15)) * LDH2 + kc * 16 + (lane >> 4) * 8) * 2;
            ldsm_x4(qf[0], qf[1], qf[2], qf[3], aaddr);
#pragma unroll
            for (int g = 0; g < 4; g++) {
                uint32_t kf[4];
                uint32_t baddr = kB +
                    ((g * 16 + (lane & 15)) * LDH2 + kc * 16 + (lane >> 4) * 8) * 2;
                ldsm_x4(kf[0], kf[1], kf[2], kf[3], baddr);
                mma_f16(sacc[2 * g],     qf, kf[0], kf[2]);
                mma_f16(sacc[2 * g + 1], qf, kf[1], kf[3]);
            }
        }

        if (kt == qtile) {
            int row0 = w * 16 + gid;
#pragma unroll
            for (int s8 = 0; s8 < 8; s8++) {
                int cb = s8 * 8 + tig * 2;
                if (cb     > row0)     sacc[s8][0] = -INFINITY;
                if (cb + 1 > row0)     sacc[s8][1] = -INFINITY;
                if (cb     > row0 + 8) sacc[s8][2] = -INFINITY;
                if (cb + 1 > row0 + 8) sacc[s8][3] = -INFINITY;
            }
        }

        float mx0 = -INFINITY, mx1 = -INFINITY;
#pragma unroll
        for (int s8 = 0; s8 < 8; s8++) {
            mx0 = fmaxf(mx0, fmaxf(sacc[s8][0], sacc[s8][1]));
            mx1 = fmaxf(mx1, fmaxf(sacc[s8][2], sacc[s8][3]));
        }
#pragma unroll
        for (int o = 1; o < 4; o <<= 1) {
            mx0 = fmaxf(mx0, __shfl_xor_sync(0xffffffffu, mx0, o));
            mx1 = fmaxf(mx1, __shfl_xor_sync(0xffffffffu, mx1, o));
        }
        float mn0 = fmaxf(m0, mx0), mn1 = fmaxf(m1, mx1);
        float f0 = __expf(m0 - mn0), f1 = __expf(m1 - mn1);
        float rs0 = 0.0f, rs1 = 0.0f;
#pragma unroll
        for (int s8 = 0; s8 < 8; s8++) {
            sacc[s8][0] = __expf(sacc[s8][0] - mn0);
            sacc[s8][1] = __expf(sacc[s8][1] - mn0);
            sacc[s8][2] = __expf(sacc[s8][2] - mn1);
            sacc[s8][3] = __expf(sacc[s8][3] - mn1);
            rs0 += sacc[s8][0] + sacc[s8][1];
            rs1 += sacc[s8][2] + sacc[s8][3];
        }
#pragma unroll
        for (int o = 1; o < 4; o <<= 1) {
            rs0 += __shfl_xor_sync(0xffffffffu, rs0, o);
            rs1 += __shfl_xor_sync(0xffffffffu, rs1, o);
        }
        l0 = l0 * f0 + rs0; m0 = mn0;
        l1 = l1 * f1 + rs1; m1 = mn1;
#pragma unroll
        for (int t = 0; t < 16; t++) {
            oacc[t][0] *= f0; oacc[t][1] *= f0;
            oacc[t][2] *= f1; oacc[t][3] *= f1;
        }

        // Repack P to fp16 A-fragments
        uint32_t aP[4][4];
#pragma unroll
        for (int j = 0; j < 4; j++) {
#pragma unroll
            for (int half = 0; half < 2; half++) {
                int t = 2 * j + half;
                __half2 p01 = __floats2half2_rn(sacc[t][0], sacc[t][1]);
                __half2 p23 = __floats2half2_rn(sacc[t][2], sacc[t][3]);
                aP[j][2 * half]     = *(uint32_t*)&p01;
                aP[j][2 * half + 1] = *(uint32_t*)&p23;
            }
        }

        // O += P V (fp16, single term)
#pragma unroll
        for (int j = 0; j < 4; j++) {
#pragma unroll
            for (int g = 0; g < 8; g++) {
                uint32_t vf[4];
                uint32_t baddr = vB +
                    ((j * 16 + (lane & 15)) * LDH2 + g * 16 + (lane >> 4) * 8) * 2;
                ldsm_x4_t(vf[0], vf[1], vf[2], vf[3], baddr);
                mma_f16(oacc[2 * g],     aP[j], vf[0], vf[1]);
                mma_f16(oacc[2 * g + 1], aP[j], vf[2], vf[3]);
            }
        }
        __syncthreads();   // protect stage reuse by next iteration's load
    }

    // Epilogue: write plain fp16 ctx [M, DIM].
    float inv0 = 1.0f / l0, inv1 = 1.0f / l1;
    int r0g = qbase + w * 16 + gid;
    size_t m0r = (size_t)(b * Tt + r0g) * DIM;
    size_t m1r = (size_t)(b * Tt + r0g + 8) * DIM;
#pragma unroll
    for (int t = 0; t < 16; t++) {
        int col = h * HD + t * 8 + tig * 2;
        *(__half2*)&ctxs[m0r + col] =
            __floats2half2_rn(oacc[t][0] * inv0, oacc[t][1] * inv0);
        *(__half2*)&ctxs[m1r + col] =
            __floats2half2_rn(oacc[t][2] * inv1, oacc[t][3] * inv1);
    }
}

// ---------------------------------------------------------------------------
// Launch
// ---------------------------------------------------------------------------
extern "C" void kernel_launch(void* const* d_in, const int* in_sizes, int n_in,
                              void* d_out, int out_size) {
    const float* x    = (const float*)d_in[0];
    const float* Wq   = (const float*)d_in[1];
    const float* Wkv  = (const float*)d_in[2];
    const float* Wo   = (const float*)d_in[3];
    const float* cosb = (const float*)d_in[4];
    const float* sinb = (const float*)d_in[5];
    float* out = (float*)d_out;

    float *qbuf, *kvbuf;
    __half *xs, *ctxs, *wqs, *wkvs, *wos, *qsb, *ksb, *vsb;
    cudaGetSymbolAddress((void**)&qbuf,   g_q);
    cudaGetSymbolAddress((void**)&kvbuf,  g_kv);
    cudaGetSymbolAddress((void**)&xs,     g_xs);
    cudaGetSymbolAddress((void**)&ctxs,   g_ctxs);
    cudaGetSymbolAddress((void**)&wqs,    g_wqs);
    cudaGetSymbolAddress((void**)&wkvs,   g_wkvs);
    cudaGetSymbolAddress((void**)&wos,    g_wos);
    cudaGetSymbolAddress((void**)&qsb,    g_qs16);
    cudaGetSymbolAddress((void**)&ksb,    g_ks16);
    cudaGetSymbolAddress((void**)&vsb,    g_vs16);

    cudaFuncSetAttribute(hgemm256, cudaFuncAttributeMaxDynamicSharedMemorySize,
                         GEMM_SMEM);
    cudaFuncSetAttribute(flash_tc, cudaFuncAttributeMaxDynamicSharedMemorySize,
                         FLASH_SMEM);

    const int M = MROWS;  // 4096

    // Conversions (all plain fp16)
    conv_h<<<(M * DIM / 4 + 255) / 256, 256>>>(x, xs, M * DIM);
    conv_h<<<(DIM * DIM / 4 + 255) / 256, 256>>>(Wq, wqs, DIM * DIM);
    conv_h<<<(DIM * NKV / 4 + 255) / 256, 256>>>(Wkv, wkvs, DIM * NKV);
    conv_h<<<(DIM * DIM / 4 + 255) / 256, 256>>>(Wo, wos, DIM * DIM);

    // q = x @ Wq ; kv = x @ Wkv
    hgemm256<<<dim3(DIM / 256, M / 128), 256, GEMM_SMEM>>>(xs, wqs, qbuf, M, DIM, DIM);
    hgemm256<<<dim3(NKV / 256, M / 128), 256, GEMM_SMEM>>>(xs, wkvs, kvbuf, M, NKV, DIM);

    // fused rope + fp16 relayout
    {
        int total = Bb * Tt * Hh * 64 + Bb * Tt * KVH * 64 + Bb * Tt * KVH * 128;
        prep_kernel<<<(total + 255) / 256, 256>>>(qbuf, kvbuf, cosb, sinb,
                                                  qsb, ksb, vsb);
    }

    // attention (fp16 single-term) -> fp16 ctx
    flash_tc<<<dim3(Tt / 64, Hh, Bb), 128, FLASH_SMEM>>>(qsb, ksb, vsb, ctxs);

    // out = ctx @ Wo
    hgemm256<<<dim3(DIM / 256, M / 128), 256, GEMM_SMEM>>>(ctxs, wos, out, M, DIM, DIM);
}